// round 4
// baseline (speedup 1.0000x reference)
#include <cuda_runtime.h>
#include <cuda_bf16.h>
#include <math.h>

// ---------------- problem constants ----------------
#define BB   2
#define TT   1024
#define DD   768
#define HH   12
#define HDIM 64
#define LL   4
#define VV   50257
#define MM   (BB*TT)      // 2048
#define D3   (3*DD)       // 2304
#define D4   (4*DD)       // 3072

// ---------------- GEMM config ----------------
#define BM 128
#define BN 128
#define BK 32
#define STAGES 3
#define ASTRIDE 40                         // bf16 elems per smem row (32 + 8 pad)
#define MAT_BYTES (128 * ASTRIDE * 2)      // 10240 B per matrix per stage
#define STAGE_BYTES (4 * MAT_BYTES)        // Ahi, Alo, Bhi, Blo
#define SMEM_DYN (STAGES * STAGE_BYTES)    // 122880

// ---------------- scratch (device globals; no allocations) ----------
__device__ float g_x   [MM * DD];
__device__ float g_qkv [MM * D3];

__device__ __align__(16) __nv_bfloat16 g_h_hi   [MM * DD];
__device__ __align__(16) __nv_bfloat16 g_h_lo   [MM * DD];
__device__ __align__(16) __nv_bfloat16 g_attn_hi[MM * DD];
__device__ __align__(16) __nv_bfloat16 g_attn_lo[MM * DD];
__device__ __align__(16) __nv_bfloat16 g_fc_hi  [MM * D4];
__device__ __align__(16) __nv_bfloat16 g_fc_lo  [MM * D4];

__device__ __align__(16) __nv_bfloat16 g_attnwT_hi[LL * D3 * DD];
__device__ __align__(16) __nv_bfloat16 g_attnwT_lo[LL * D3 * DD];
__device__ __align__(16) __nv_bfloat16 g_projwT_hi[LL * DD * DD];
__device__ __align__(16) __nv_bfloat16 g_projwT_lo[LL * DD * DD];
__device__ __align__(16) __nv_bfloat16 g_fcwT_hi  [LL * D4 * DD];
__device__ __align__(16) __nv_bfloat16 g_fcwT_lo  [LL * D4 * DD];
__device__ __align__(16) __nv_bfloat16 g_outwT_hi [LL * DD * D4];
__device__ __align__(16) __nv_bfloat16 g_outwT_lo [LL * DD * D4];
__device__ __align__(16) __nv_bfloat16 g_wte_hi   [VV * DD];
__device__ __align__(16) __nv_bfloat16 g_wte_lo   [VV * DD];

// ---------------- helpers ----------------
__device__ __forceinline__ void split2(float x, __nv_bfloat16& hi, __nv_bfloat16& lo) {
    hi = __float2bfloat16_rn(x);
    lo = __float2bfloat16_rn(x - __bfloat162float(hi));
}

__device__ __forceinline__ void mma_bf16(float* c, const unsigned* a, const unsigned* b) {
    asm volatile(
        "mma.sync.aligned.m16n8k16.row.col.f32.bf16.bf16.f32 "
        "{%0,%1,%2,%3}, {%4,%5,%6,%7}, {%8,%9}, {%0,%1,%2,%3};"
        : "+f"(c[0]), "+f"(c[1]), "+f"(c[2]), "+f"(c[3])
        : "r"(a[0]), "r"(a[1]), "r"(a[2]), "r"(a[3]), "r"(b[0]), "r"(b[1]));
}

#define CP_ASYNC16(saddr, gaddr, sz) \
    asm volatile("cp.async.cg.shared.global [%0], [%1], 16, %2;" \
                 :: "r"(saddr), "l"(gaddr), "r"(sz) : "memory")
#define CP_COMMIT() asm volatile("cp.async.commit_group;" ::: "memory")
#define CP_WAIT1()  asm volatile("cp.async.wait_group 1;" ::: "memory")

// ---------------- conversion kernels ----------------
__global__ void conv_split_kernel(const float* __restrict__ src,
                                  __nv_bfloat16* __restrict__ dhi,
                                  __nv_bfloat16* __restrict__ dlo, int n) {
    int i = blockIdx.x * blockDim.x + threadIdx.x;
    if (i >= n) return;
    __nv_bfloat16 h, l;
    split2(src[i], h, l);
    dhi[i] = h; dlo[i] = l;
}

// transpose + split: src [K][N] fp32 -> dst [N][K] bf16 hi/lo
__global__ void conv_transpose_kernel(const float* __restrict__ src,
                                      __nv_bfloat16* __restrict__ dhi,
                                      __nv_bfloat16* __restrict__ dlo,
                                      int Kd, int Nd) {
    __shared__ float t[32][33];
    int n0 = blockIdx.x * 32, k0 = blockIdx.y * 32;
    int tx = threadIdx.x, ty = threadIdx.y;   // 32 x 8
#pragma unroll
    for (int i = 0; i < 4; i++) {
        int k = k0 + ty + i * 8, n = n0 + tx;
        if (k < Kd && n < Nd) t[ty + i * 8][tx] = src[(size_t)k * Nd + n];
    }
    __syncthreads();
#pragma unroll
    for (int i = 0; i < 4; i++) {
        int n = n0 + ty + i * 8, k = k0 + tx;
        if (n < Nd && k < Kd) {
            __nv_bfloat16 h, l;
            split2(t[tx][ty + i * 8], h, l);
            dhi[(size_t)n * Kd + k] = h;
            dlo[(size_t)n * Kd + k] = l;
        }
    }
}

// ---------------- embedding ----------------
__global__ void embed_kernel(const int* __restrict__ ids,
                             const float* __restrict__ wte,
                             const float* __restrict__ wpe,
                             float* __restrict__ x) {
    int idx = blockIdx.x * blockDim.x + threadIdx.x;
    if (idx >= MM * DD) return;
    int d  = idx % DD;
    int bt = idx / DD;
    int t  = bt % TT;
    x[idx] = wte[(size_t)ids[bt] * DD + d] + wpe[(size_t)t * DD + d];
}

// ---------------- layernorm: fp32 in -> bf16 hi/lo out -------------
__global__ void layernorm_split_kernel(const float* __restrict__ x,
                                       const float* __restrict__ g,
                                       const float* __restrict__ b,
                                       __nv_bfloat16* __restrict__ ohi,
                                       __nv_bfloat16* __restrict__ olo) {
    int row = blockIdx.x;
    int tid = threadIdx.x;
    __shared__ float red[256];
    __shared__ float s_mu, s_rstd;
    const float* xr = x + (size_t)row * DD;

    float s = 0.f;
    for (int d = tid; d < DD; d += 256) s += xr[d];
    red[tid] = s; __syncthreads();
    for (int o = 128; o > 0; o >>= 1) {
        if (tid < o) red[tid] += red[tid + o];
        __syncthreads();
    }
    if (tid == 0) s_mu = red[0] / DD;
    __syncthreads();
    float mu = s_mu;

    float v = 0.f;
    for (int d = tid; d < DD; d += 256) { float t = xr[d] - mu; v += t * t; }
    red[tid] = v; __syncthreads();
    for (int o = 128; o > 0; o >>= 1) {
        if (tid < o) red[tid] += red[tid + o];
        __syncthreads();
    }
    if (tid == 0) s_rstd = rsqrtf(red[0] / DD + 1e-5f);
    __syncthreads();
    float rstd = s_rstd;

    for (int d = tid; d < DD; d += 256) {
        float val = g[d] * (xr[d] - mu) * rstd + b[d];
        __nv_bfloat16 h, l;
        split2(val, h, l);
        ohi[(size_t)row * DD + d] = h;
        olo[(size_t)row * DD + d] = l;
    }
}

// ---------------- bf16 hi/lo 3-term GEMM (mma.sync m16n8k16) ----------------
// C[M,N] = Ahi/lo[M,K] @ (Bhi/lo[N,K])^T  (+bias)(+gelu)(+residual)
// 256 threads / 8 warps; warp tile 64x32; cp.async 3-stage pipeline.
// Requires M % 128 == 0, K % 32 == 0. N-tail predicated (zero-filled loads).
template <int ACT, int WRITE_SPLIT, int HAS_RES>
__global__ void __launch_bounds__(256)
gemm_hl(const __nv_bfloat16* __restrict__ Ahi, const __nv_bfloat16* __restrict__ Alo,
        const __nv_bfloat16* __restrict__ Bhi, const __nv_bfloat16* __restrict__ Blo,
        const float* __restrict__ bias, const float* __restrict__ residual,
        float* __restrict__ C,
        __nv_bfloat16* __restrict__ Chi, __nv_bfloat16* __restrict__ Clo,
        int N, int K) {
    extern __shared__ char sm[];

    const int tid  = threadIdx.x;
    const int lane = tid & 31;
    const int wid  = tid >> 5;
    const int wm   = (wid & 1) * 64;
    const int wn   = (wid >> 1) * 32;
    const int gp   = lane >> 2;
    const int tg   = lane & 3;
    const int row0 = blockIdx.y * BM;
    const int col0 = blockIdx.x * BN;
    const int nk   = K / BK;

    // loader mapping: thread -> one row (A and B), 16-elem half
    const int lr = tid >> 1;            // 0..127
    const int lc = (tid & 1) * 16;      // 0 or 16
    const size_t aoff = (size_t)(row0 + lr) * K + lc;
    const int nrow = col0 + lr;
    const unsigned bsz = (nrow < N) ? 16u : 0u;
    const size_t boff = (size_t)((nrow < N) ? nrow : 0) * K + lc;
    const unsigned s_row = (unsigned)((lr * ASTRIDE + lc) * 2);   // byte offset in matrix

    float acc[4][4][4];
#pragma unroll
    for (int a = 0; a < 4; a++)
#pragma unroll
        for (int b = 0; b < 4; b++)
#pragma unroll
            for (int c = 0; c < 4; c++) acc[a][b][c] = 0.f;

    // ---- stage loader ----
    auto load_stage = [&](int slot, int k0) {
        unsigned base = (unsigned)__cvta_generic_to_shared(sm) + slot * STAGE_BYTES;
        const char* gah = (const char*)(Ahi + aoff + k0);
        const char* gal = (const char*)(Alo + aoff + k0);
        const char* gbh = (const char*)(Bhi + boff + k0);
        const char* gbl = (const char*)(Blo + boff + k0);
        unsigned sa = base + s_row;
        CP_ASYNC16(sa,                  gah,      16u);
        CP_ASYNC16(sa + 16,             gah + 16, 16u);
        CP_ASYNC16(sa + MAT_BYTES,      gal,      16u);
        CP_ASYNC16(sa + MAT_BYTES + 16, gal + 16, 16u);
        unsigned sb = base + 2 * MAT_BYTES + s_row;
        CP_ASYNC16(sb,                  gbh,      bsz);
        CP_ASYNC16(sb + 16,             gbh + 16, bsz);
        CP_ASYNC16(sb + MAT_BYTES,      gbl,      bsz);
        CP_ASYNC16(sb + MAT_BYTES + 16, gbl + 16, bsz);
    };

    // prologue
#pragma unroll
    for (int p = 0; p < STAGES - 1; p++) {
        if (p < nk) load_stage(p, p * BK);
        CP_COMMIT();
    }

    for (int kt = 0; kt < nk; kt++) {
        int ldk = kt + STAGES - 1;
        if (ldk < nk) load_stage(ldk % STAGES, ldk * BK);
        CP_COMMIT();
        CP_WAIT1();
        __syncthreads();

        const char* st = sm + (kt % STAGES) * STAGE_BYTES;
        const char* sAh = st;
        const char* sAl = st + MAT_BYTES;
        const char* sBh = st + 2 * MAT_BYTES;
        const char* sBl = st + 3 * MAT_BYTES;

#pragma unroll
        for (int ks = 0; ks < 2; ks++) {
            const int cb = ks * 16 + tg * 2;
            unsigned ah[4][4], al[4][4], bh[4][2], bl[4][2];
#pragma unroll
            for (int mi = 0; mi < 4; mi++) {
                int r = wm + mi * 16 + gp;
                ah[mi][0] = *(const unsigned*)(sAh + (r * ASTRIDE + cb) * 2);
                ah[mi][1] = *(const unsigned*)(sAh + ((r + 8) * ASTRIDE + cb) * 2);
                ah[mi][2] = *(const unsigned*)(sAh + (r * ASTRIDE + cb + 8) * 2);
                ah[mi][3] = *(const unsigned*)(sAh + ((r + 8) * ASTRIDE + cb + 8) * 2);
                al[mi][0] = *(const unsigned*)(sAl + (r * ASTRIDE + cb) * 2);
                al[mi][1] = *(const unsigned*)(sAl + ((r + 8) * ASTRIDE + cb) * 2);
                al[mi][2] = *(const unsigned*)(sAl + (r * ASTRIDE + cb + 8) * 2);
                al[mi][3] = *(const unsigned*)(sAl + ((r + 8) * ASTRIDE + cb + 8) * 2);
            }
#pragma unroll
            for (int ni = 0; ni < 4; ni++) {
                int n = wn + ni * 8 + gp;
                bh[ni][0] = *(const unsigned*)(sBh + (n * ASTRIDE + cb) * 2);
                bh[ni][1] = *(const unsigned*)(sBh + (n * ASTRIDE + cb + 8) * 2);
                bl[ni][0] = *(const unsigned*)(sBl + (n * ASTRIDE + cb) * 2);
                bl[ni][1] = *(const unsigned*)(sBl + (n * ASTRIDE + cb + 8) * 2);
            }
#pragma unroll
            for (int mi = 0; mi < 4; mi++)
#pragma unroll
                for (int ni = 0; ni < 4; ni++) {
                    mma_bf16(acc[mi][ni], ah[mi], bh[ni]);
                    mma_bf16(acc[mi][ni], al[mi], bh[ni]);
                    mma_bf16(acc[mi][ni], ah[mi], bl[ni]);
                }
        }
        __syncthreads();
    }

    // ---- epilogue ----
#pragma unroll
    for (int mi = 0; mi < 4; mi++) {
        int rb = row0 + wm + mi * 16 + gp;
#pragma unroll
        for (int ni = 0; ni < 4; ni++) {
            int c = col0 + wn + ni * 8 + tg * 2;
            if (c >= N) continue;
            bool c1ok = (c + 1 < N);
#pragma unroll
            for (int half = 0; half < 2; half++) {
                int r = rb + half * 8;
                float v0 = acc[mi][ni][half * 2 + 0];
                float v1 = acc[mi][ni][half * 2 + 1];
                if (bias) { v0 += bias[c]; if (c1ok) v1 += bias[c + 1]; }
                if (ACT) {
                    v0 = 0.5f * v0 * (1.0f + erff(v0 * 0.70710678118654752f));
                    v1 = 0.5f * v1 * (1.0f + erff(v1 * 0.70710678118654752f));
                }
                if (WRITE_SPLIT) {
                    __nv_bfloat16 h0, l0, h1, l1;
                    split2(v0, h0, l0); split2(v1, h1, l1);
                    *reinterpret_cast<__nv_bfloat162*>(&Chi[(size_t)r * N + c]) =
                        __nv_bfloat162(h0, h1);
                    *reinterpret_cast<__nv_bfloat162*>(&Clo[(size_t)r * N + c]) =
                        __nv_bfloat162(l0, l1);
                } else {
                    if (HAS_RES) {
                        v0 += residual[(size_t)r * N + c];
                        if (c1ok) v1 += residual[(size_t)r * N + c + 1];
                    }
                    C[(size_t)r * N + c] = v0;
                    if (c1ok) C[(size_t)r * N + c + 1] = v1;
                }
            }
        }
    }
}

// ---------------- attention: one block per (q, head, batch) ----------------
__global__ void attention_kernel(const float* __restrict__ qkv,
                                 __nv_bfloat16* __restrict__ ohi,
                                 __nv_bfloat16* __restrict__ olo) {
    int q = blockIdx.x, h = blockIdx.y, b = blockIdx.z;
    int tid = threadIdx.x;
    __shared__ float sq[HDIM];
    __shared__ float ss[TT];
    __shared__ float red[256];

    const float* qptr = qkv + ((size_t)(b * TT + q)) * D3 + h * HDIM;
    if (tid < HDIM) sq[tid] = qptr[tid];
    __syncthreads();

    float lmax = -1e30f;
    for (int k = tid; k <= q; k += 256) {
        const float* kptr = qkv + ((size_t)(b * TT + k)) * D3 + DD + h * HDIM;
        float s = 0.f;
#pragma unroll
        for (int d = 0; d < HDIM; d++) s += sq[d] * kptr[d];
        s *= 0.125f;
        ss[k] = s;
        lmax = fmaxf(lmax, s);
    }
    red[tid] = lmax; __syncthreads();
    for (int o = 128; o > 0; o >>= 1) {
        if (tid < o) red[tid] = fmaxf(red[tid], red[tid + o]);
        __syncthreads();
    }
    float mx = red[0];
    __syncthreads();

    float lsum = 0.f;
    for (int k = tid; k <= q; k += 256) {
        float e = expf(ss[k] - mx);
        ss[k] = e;
        lsum += e;
    }
    red[tid] = lsum; __syncthreads();
    for (int o = 128; o > 0; o >>= 1) {
        if (tid < o) red[tid] += red[tid + o];
        __syncthreads();
    }
    float inv = 1.0f / red[0];

    if (tid < HDIM) {
        const float* vbase = qkv + (size_t)b * TT * D3 + 2 * DD + h * HDIM + tid;
        float acc = 0.f;
        for (int k = 0; k <= q; k++)
            acc += ss[k] * vbase[(size_t)k * D3];
        float v = acc * inv;
        __nv_bfloat16 hi, lo;
        split2(v, hi, lo);
        size_t oi = ((size_t)(b * TT + q)) * DD + h * HDIM + tid;
        ohi[oi] = hi; olo[oi] = lo;
    }
}

// ---------------- launch ----------------
extern "C" void kernel_launch(void* const* d_in, const int* in_sizes, int n_in,
                              void* d_out, int out_size) {
    const int*   ids    = (const int*)  d_in[0];
    const float* wte    = (const float*)d_in[1];
    const float* wpe    = (const float*)d_in[2];
    const float* ln1_g  = (const float*)d_in[3];
    const float* ln1_b  = (const float*)d_in[4];
    const float* attn_w = (const float*)d_in[5];
    const float* attn_b = (const float*)d_in[6];
    const float* proj_w = (const float*)d_in[7];
    const float* proj_b = (const float*)d_in[8];
    const float* ln2_g  = (const float*)d_in[9];
    const float* ln2_b  = (const float*)d_in[10];
    const float* fc_w   = (const float*)d_in[11];
    const float* fc_b   = (const float*)d_in[12];
    const float* out_w  = (const float*)d_in[13];
    const float* out_b  = (const float*)d_in[14];
    const float* lnf_g  = (const float*)d_in[15];
    const float* lnf_b  = (const float*)d_in[16];
    float* logits = (float*)d_out;

    float *x, *qkv;
    __nv_bfloat16 *h_hi, *h_lo, *at_hi, *at_lo, *fc_hi, *fc_lo;
    __nv_bfloat16 *awT_hi, *awT_lo, *pwT_hi, *pwT_lo, *fwT_hi, *fwT_lo, *owT_hi, *owT_lo;
    __nv_bfloat16 *wte_hi, *wte_lo;
    cudaGetSymbolAddress((void**)&x,      g_x);
    cudaGetSymbolAddress((void**)&qkv,    g_qkv);
    cudaGetSymbolAddress((void**)&h_hi,   g_h_hi);
    cudaGetSymbolAddress((void**)&h_lo,   g_h_lo);
    cudaGetSymbolAddress((void**)&at_hi,  g_attn_hi);
    cudaGetSymbolAddress((void**)&at_lo,  g_attn_lo);
    cudaGetSymbolAddress((void**)&fc_hi,  g_fc_hi);
    cudaGetSymbolAddress((void**)&fc_lo,  g_fc_lo);
    cudaGetSymbolAddress((void**)&awT_hi, g_attnwT_hi);
    cudaGetSymbolAddress((void**)&awT_lo, g_attnwT_lo);
    cudaGetSymbolAddress((void**)&pwT_hi, g_projwT_hi);
    cudaGetSymbolAddress((void**)&pwT_lo, g_projwT_lo);
    cudaGetSymbolAddress((void**)&fwT_hi, g_fcwT_hi);
    cudaGetSymbolAddress((void**)&fwT_lo, g_fcwT_lo);
    cudaGetSymbolAddress((void**)&owT_hi, g_outwT_hi);
    cudaGetSymbolAddress((void**)&owT_lo, g_outwT_lo);
    cudaGetSymbolAddress((void**)&wte_hi, g_wte_hi);
    cudaGetSymbolAddress((void**)&wte_lo, g_wte_lo);

    cudaFuncSetAttribute(gemm_hl<0,0,0>, cudaFuncAttributeMaxDynamicSharedMemorySize, SMEM_DYN);
    cudaFuncSetAttribute(gemm_hl<0,0,1>, cudaFuncAttributeMaxDynamicSharedMemorySize, SMEM_DYN);
    cudaFuncSetAttribute(gemm_hl<1,1,0>, cudaFuncAttributeMaxDynamicSharedMemorySize, SMEM_DYN);

    // ---- weight conversion (transpose + hi/lo split) ----
    dim3 tb(32, 8);
    for (int l = 0; l < LL; l++) {
        conv_transpose_kernel<<<dim3(D3 / 32, DD / 32), tb>>>(
            attn_w + (size_t)l * DD * D3, awT_hi + (size_t)l * D3 * DD,
            awT_lo + (size_t)l * D3 * DD, DD, D3);
        conv_transpose_kernel<<<dim3(DD / 32, DD / 32), tb>>>(
            proj_w + (size_t)l * DD * DD, pwT_hi + (size_t)l * DD * DD,
            pwT_lo + (size_t)l * DD * DD, DD, DD);
        conv_transpose_kernel<<<dim3(D4 / 32, DD / 32), tb>>>(
            fc_w + (size_t)l * DD * D4, fwT_hi + (size_t)l * D4 * DD,
            fwT_lo + (size_t)l * D4 * DD, DD, D4);
        conv_transpose_kernel<<<dim3(DD / 32, D4 / 32), tb>>>(
            out_w + (size_t)l * D4 * DD, owT_hi + (size_t)l * DD * D4,
            owT_lo + (size_t)l * DD * D4, D4, DD);
    }
    conv_split_kernel<<<(VV * DD + 255) / 256, 256>>>(wte, wte_hi, wte_lo, VV * DD);

    embed_kernel<<<(MM * DD + 255) / 256, 256>>>(ids, wte, wpe, x);

    const dim3 gQKV(D3 / BN, MM / BM), gPROJ(DD / BN, MM / BM),
               gFC(D4 / BN, MM / BM),  gOUT(DD / BN, MM / BM),
               gLM((VV + BN - 1) / BN, MM / BM);

    for (int l = 0; l < LL; l++) {
        // --- attention block ---
        layernorm_split_kernel<<<MM, 256>>>(x, ln1_g + l * DD, ln1_b + l * DD, h_hi, h_lo);

        gemm_hl<0,0,0><<<gQKV, 256, SMEM_DYN>>>(
            h_hi, h_lo, awT_hi + (size_t)l * D3 * DD, awT_lo + (size_t)l * D3 * DD,
            attn_b + (size_t)l * D3, nullptr, qkv, nullptr, nullptr, D3, DD);

        attention_kernel<<<dim3(TT, HH, BB), 256>>>(qkv, at_hi, at_lo);

        gemm_hl<0,0,1><<<gPROJ, 256, SMEM_DYN>>>(
            at_hi, at_lo, pwT_hi + (size_t)l * DD * DD, pwT_lo + (size_t)l * DD * DD,
            proj_b + (size_t)l * DD, x, x, nullptr, nullptr, DD, DD);

        // --- mlp block ---
        layernorm_split_kernel<<<MM, 256>>>(x, ln2_g + l * DD, ln2_b + l * DD, h_hi, h_lo);

        gemm_hl<1,1,0><<<gFC, 256, SMEM_DYN>>>(
            h_hi, h_lo, fwT_hi + (size_t)l * D4 * DD, fwT_lo + (size_t)l * D4 * DD,
            fc_b + (size_t)l * D4, nullptr, nullptr, fc_hi, fc_lo, D4, DD);

        gemm_hl<0,0,1><<<gOUT, 256, SMEM_DYN>>>(
            fc_hi, fc_lo, owT_hi + (size_t)l * DD * D4, owT_lo + (size_t)l * DD * D4,
            out_b + (size_t)l * DD, x, x, nullptr, nullptr, DD, D4);
    }

    layernorm_split_kernel<<<MM, 256>>>(x, lnf_g, lnf_b, h_hi, h_lo);

    // lm_head: logits = h @ wte^T
    gemm_hl<0,0,0><<<gLM, 256, SMEM_DYN>>>(
        h_hi, h_lo, wte_hi, wte_lo,
        nullptr, nullptr, logits, nullptr, nullptr, VV, DD);
}

// round 5
// speedup vs baseline: 1.0542x; 1.0542x over previous
#include <cuda_runtime.h>
#include <cuda_bf16.h>
#include <cuda_fp16.h>
#include <math.h>

// ---------------- problem constants ----------------
#define BB   2
#define TT   1024
#define DD   768
#define HH   12
#define HDIM 64
#define LL   4
#define VV   50257
#define MM   (BB*TT)      // 2048
#define D3   (3*DD)       // 2304
#define D4   (4*DD)       // 3072

// ---------------- GEMM config ----------------
#define BM 128
#define BN 128
#define BK 32
#define STAGES 3
#define ASTRIDE 40                          // fp16 elems per smem row (32 + 8 pad)
#define MAT_BYTES (128 * ASTRIDE * 2)       // 10240 B per matrix per stage

// ---------------- scratch (device globals; no allocations) ----------
__device__ float g_x   [MM * DD];
__device__ float g_qkv [MM * D3];

__device__ __align__(16) __half g_h_hi   [MM * DD];
__device__ __align__(16) __half g_h_lo   [MM * DD];
__device__ __align__(16) __half g_attn_hi[MM * DD];
__device__ __align__(16) __half g_attn_lo[MM * DD];
__device__ __align__(16) __half g_fc_hi  [MM * D4];
__device__ __align__(16) __half g_fc_lo  [MM * D4];

__device__ __align__(16) __half g_attnwT_hi[LL * D3 * DD];
__device__ __align__(16) __half g_attnwT_lo[LL * D3 * DD];
__device__ __align__(16) __half g_projwT_hi[LL * DD * DD];
__device__ __align__(16) __half g_projwT_lo[LL * DD * DD];
__device__ __align__(16) __half g_fcwT_hi  [LL * D4 * DD];
__device__ __align__(16) __half g_fcwT_lo  [LL * D4 * DD];
__device__ __align__(16) __half g_outwT_hi [LL * DD * D4];
__device__ __align__(16) __half g_outwT_lo [LL * DD * D4];
__device__ __align__(16) __half g_wte_h    [VV * DD];

// ---------------- helpers ----------------
__device__ __forceinline__ void split2h(float x, __half& hi, __half& lo) {
    hi = __float2half_rn(x);
    lo = __float2half_rn(x - __half2float(hi));
}

__device__ __forceinline__ void mma_f16(float* c, const unsigned* a, const unsigned* b) {
    asm volatile(
        "mma.sync.aligned.m16n8k16.row.col.f32.f16.f16.f32 "
        "{%0,%1,%2,%3}, {%4,%5,%6,%7}, {%8,%9}, {%0,%1,%2,%3};"
        : "+f"(c[0]), "+f"(c[1]), "+f"(c[2]), "+f"(c[3])
        : "r"(a[0]), "r"(a[1]), "r"(a[2]), "r"(a[3]), "r"(b[0]), "r"(b[1]));
}

#define LDSM_X4(r0, r1, r2, r3, addr) \
    asm volatile("ldmatrix.sync.aligned.m8n8.x4.shared.b16 {%0,%1,%2,%3}, [%4];" \
                 : "=r"(r0), "=r"(r1), "=r"(r2), "=r"(r3) : "r"(addr))

#define CP_ASYNC16(saddr, gaddr, sz) \
    asm volatile("cp.async.cg.shared.global [%0], [%1], 16, %2;" \
                 :: "r"(saddr), "l"(gaddr), "r"(sz) : "memory")
#define CP_COMMIT() asm volatile("cp.async.commit_group;" ::: "memory")
#define CP_WAIT1()  asm volatile("cp.async.wait_group 1;" ::: "memory")

// ---------------- conversion kernels ----------------
// wte fp32 -> fp16 single (lm-head B)
__global__ void conv_wte_kernel(const float* __restrict__ src,
                                __half* __restrict__ dst, int n) {
    int i = blockIdx.x * blockDim.x + threadIdx.x;
    if (i < n) dst[i] = __float2half_rn(src[i]);
}

// batched transpose + split: src [l][K][N] fp32 -> dst [l][N][K] fp16 hi/lo
__global__ void conv_transpose_kernel(const float* __restrict__ src,
                                      __half* __restrict__ dhi,
                                      __half* __restrict__ dlo,
                                      int Kd, int Nd) {
    int l = blockIdx.z;
    src += (size_t)l * Kd * Nd;
    dhi += (size_t)l * Nd * Kd;
    dlo += (size_t)l * Nd * Kd;
    __shared__ float t[32][33];
    int n0 = blockIdx.x * 32, k0 = blockIdx.y * 32;
    int tx = threadIdx.x, ty = threadIdx.y;   // 32 x 8
#pragma unroll
    for (int i = 0; i < 4; i++) {
        int k = k0 + ty + i * 8, n = n0 + tx;
        if (k < Kd && n < Nd) t[ty + i * 8][tx] = src[(size_t)k * Nd + n];
    }
    __syncthreads();
#pragma unroll
    for (int i = 0; i < 4; i++) {
        int n = n0 + ty + i * 8, k = k0 + tx;
        if (n < Nd && k < Kd) {
            __half h, lo;
            split2h(t[tx][ty + i * 8], h, lo);
            dhi[(size_t)n * Kd + k] = h;
            dlo[(size_t)n * Kd + k] = lo;
        }
    }
}

// ---------------- embedding ----------------
__global__ void embed_kernel(const int* __restrict__ ids,
                             const float* __restrict__ wte,
                             const float* __restrict__ wpe,
                             float* __restrict__ x) {
    int idx = blockIdx.x * blockDim.x + threadIdx.x;
    if (idx >= MM * DD) return;
    int d  = idx % DD;
    int bt = idx / DD;
    int t  = bt % TT;
    x[idx] = wte[(size_t)ids[bt] * DD + d] + wpe[(size_t)t * DD + d];
}

// ---------------- layernorm: fp32 in -> fp16 hi/lo out -------------
__global__ void layernorm_split_kernel(const float* __restrict__ x,
                                       const float* __restrict__ g,
                                       const float* __restrict__ b,
                                       __half* __restrict__ ohi,
                                       __half* __restrict__ olo) {
    int row = blockIdx.x;
    int tid = threadIdx.x;
    __shared__ float red[256];
    __shared__ float s_mu, s_rstd;
    const float* xr = x + (size_t)row * DD;

    float s = 0.f;
    for (int d = tid; d < DD; d += 256) s += xr[d];
    red[tid] = s; __syncthreads();
    for (int o = 128; o > 0; o >>= 1) {
        if (tid < o) red[tid] += red[tid + o];
        __syncthreads();
    }
    if (tid == 0) s_mu = red[0] / DD;
    __syncthreads();
    float mu = s_mu;

    float v = 0.f;
    for (int d = tid; d < DD; d += 256) { float t = xr[d] - mu; v += t * t; }
    red[tid] = v; __syncthreads();
    for (int o = 128; o > 0; o >>= 1) {
        if (tid < o) red[tid] += red[tid + o];
        __syncthreads();
    }
    if (tid == 0) s_rstd = rsqrtf(red[0] / DD + 1e-5f);
    __syncthreads();
    float rstd = s_rstd;

    for (int d = tid; d < DD; d += 256) {
        float val = g[d] * (xr[d] - mu) * rstd + b[d];
        __half h, l;
        split2h(val, h, l);
        ohi[(size_t)row * DD + d] = h;
        olo[(size_t)row * DD + d] = l;
    }
}

// ---------------- fp16 GEMM (mma.sync m16n8k16 + ldmatrix) ----------------
// TERMS==3: C = Ahi.Bhi^T + Alo.Bhi^T + Ahi.Blo^T   (hi/lo split, ~fp32 accuracy)
// TERMS==1: C = Ahi.Bhi^T                           (single-pass fp16)
// A[M,K], B[N,K] fp16 row-major.  +bias (+gelu) (+residual / split-write).
// 256 threads / 8 warps; warp tile 64x32; 3-stage cp.async pipeline.
template <int TERMS, int ACT, int WRITE_SPLIT, int HAS_RES>
__global__ void __launch_bounds__(256)
gemm_hl(const __half* __restrict__ Ahi, const __half* __restrict__ Alo,
        const __half* __restrict__ Bhi, const __half* __restrict__ Blo,
        const float* __restrict__ bias, const float* __restrict__ residual,
        float* __restrict__ C,
        __half* __restrict__ Chi, __half* __restrict__ Clo,
        int N, int K) {
    constexpr int NMAT = (TERMS == 1) ? 2 : 4;
    constexpr int STAGE_BYTES = NMAT * MAT_BYTES;
    // matrix offsets in stage: [Ahi][Bhi][Alo][Blo]
    constexpr unsigned AHI_OFF = 0;
    constexpr unsigned BHI_OFF = MAT_BYTES;
    constexpr unsigned ALO_OFF = 2 * MAT_BYTES;
    constexpr unsigned BLO_OFF = 3 * MAT_BYTES;

    extern __shared__ char sm[];
    const unsigned smb = (unsigned)__cvta_generic_to_shared(sm);

    const int tid  = threadIdx.x;
    const int lane = tid & 31;
    const int wid  = tid >> 5;
    const int wm   = (wid & 1) * 64;
    const int wn   = (wid >> 1) * 32;
    const int gp   = lane >> 2;
    const int tg   = lane & 3;
    const int row0 = blockIdx.y * BM;
    const int col0 = blockIdx.x * BN;
    const int nk   = K / BK;

    // ldmatrix lane mapping
    const int lrow  = lane & 15;          // row within 16-row tile
    const int lcol8 = (lane >> 4) * 8;    // k offset 0 or 8

    // loader mapping: thread -> one row, 16-elem half
    const int lr = tid >> 1;              // 0..127
    const int lc = (tid & 1) * 16;        // 0 or 16
    const size_t aoff = (size_t)(row0 + lr) * K + lc;
    const int nrow = col0 + lr;
    const unsigned bsz = (nrow < N) ? 16u : 0u;
    const size_t boff = (size_t)((nrow < N) ? nrow : 0) * K + lc;
    const unsigned s_row = (unsigned)((lr * ASTRIDE + lc) * 2);

    float acc[4][4][4];
#pragma unroll
    for (int a = 0; a < 4; a++)
#pragma unroll
        for (int b = 0; b < 4; b++)
#pragma unroll
            for (int c = 0; c < 4; c++) acc[a][b][c] = 0.f;

    auto load_stage = [&](int slot, int k0) {
        unsigned base = smb + slot * STAGE_BYTES;
        const char* gah = (const char*)(Ahi + aoff + k0);
        const char* gbh = (const char*)(Bhi + boff + k0);
        CP_ASYNC16(base + AHI_OFF + s_row,      gah,      16u);
        CP_ASYNC16(base + AHI_OFF + s_row + 16, gah + 16, 16u);
        CP_ASYNC16(base + BHI_OFF + s_row,      gbh,      bsz);
        CP_ASYNC16(base + BHI_OFF + s_row + 16, gbh + 16, bsz);
        if (TERMS == 3) {
            const char* gal = (const char*)(Alo + aoff + k0);
            const char* gbl = (const char*)(Blo + boff + k0);
            CP_ASYNC16(base + ALO_OFF + s_row,      gal,      16u);
            CP_ASYNC16(base + ALO_OFF + s_row + 16, gal + 16, 16u);
            CP_ASYNC16(base + BLO_OFF + s_row,      gbl,      bsz);
            CP_ASYNC16(base + BLO_OFF + s_row + 16, gbl + 16, bsz);
        }
    };

#pragma unroll
    for (int p = 0; p < STAGES - 1; p++) {
        if (p < nk) load_stage(p, p * BK);
        CP_COMMIT();
    }

    for (int kt = 0; kt < nk; kt++) {
        int ldk = kt + STAGES - 1;
        if (ldk < nk) load_stage(ldk % STAGES, ldk * BK);
        CP_COMMIT();
        CP_WAIT1();
        __syncthreads();

        const unsigned st = smb + (kt % STAGES) * STAGE_BYTES;

#pragma unroll
        for (int ks = 0; ks < 2; ks++) {
            const int kb = ks * 16 + lcol8;
            unsigned ah[4][4], al[4][4], bh[4][2], bl[4][2];
#pragma unroll
            for (int mi = 0; mi < 4; mi++) {
                unsigned ad = st + AHI_OFF + ((wm + mi * 16 + lrow) * ASTRIDE + kb) * 2;
                LDSM_X4(ah[mi][0], ah[mi][1], ah[mi][2], ah[mi][3], ad);
                if (TERMS == 3) {
                    unsigned ad2 = st + ALO_OFF + ((wm + mi * 16 + lrow) * ASTRIDE + kb) * 2;
                    LDSM_X4(al[mi][0], al[mi][1], al[mi][2], al[mi][3], ad2);
                }
            }
#pragma unroll
            for (int p = 0; p < 2; p++) {
                unsigned bd = st + BHI_OFF + ((wn + p * 16 + lrow) * ASTRIDE + kb) * 2;
                unsigned t0, t1, t2, t3;
                LDSM_X4(t0, t1, t2, t3, bd);
                bh[2 * p][0] = t0; bh[2 * p + 1][0] = t1;
                bh[2 * p][1] = t2; bh[2 * p + 1][1] = t3;
                if (TERMS == 3) {
                    unsigned bd2 = st + BLO_OFF + ((wn + p * 16 + lrow) * ASTRIDE + kb) * 2;
                    LDSM_X4(t0, t1, t2, t3, bd2);
                    bl[2 * p][0] = t0; bl[2 * p + 1][0] = t1;
                    bl[2 * p][1] = t2; bl[2 * p + 1][1] = t3;
                }
            }
#pragma unroll
            for (int mi = 0; mi < 4; mi++)
#pragma unroll
                for (int ni = 0; ni < 4; ni++) {
                    mma_f16(acc[mi][ni], ah[mi], bh[ni]);
                    if (TERMS == 3) {
                        mma_f16(acc[mi][ni], al[mi], bh[ni]);
                        mma_f16(acc[mi][ni], ah[mi], bl[ni]);
                    }
                }
        }
        __syncthreads();
    }

    // ---- epilogue ----
#pragma unroll
    for (int mi = 0; mi < 4; mi++) {
        int rb = row0 + wm + mi * 16 + gp;
#pragma unroll
        for (int ni = 0; ni < 4; ni++) {
            int c = col0 + wn + ni * 8 + tg * 2;
            if (c >= N) continue;
            bool c1ok = (c + 1 < N);
#pragma unroll
            for (int half = 0; half < 2; half++) {
                int r = rb + half * 8;
                float v0 = acc[mi][ni][half * 2 + 0];
                float v1 = acc[mi][ni][half * 2 + 1];
                if (bias) { v0 += bias[c]; if (c1ok) v1 += bias[c + 1]; }
                if (ACT) {
                    v0 = 0.5f * v0 * (1.0f + erff(v0 * 0.70710678118654752f));
                    v1 = 0.5f * v1 * (1.0f + erff(v1 * 0.70710678118654752f));
                }
                if (WRITE_SPLIT) {
                    __half h0, l0, h1, l1;
                    split2h(v0, h0, l0); split2h(v1, h1, l1);
                    *reinterpret_cast<__half2*>(&Chi[(size_t)r * N + c]) = __half2(h0, h1);
                    *reinterpret_cast<__half2*>(&Clo[(size_t)r * N + c]) = __half2(l0, l1);
                } else {
                    if (HAS_RES) {
                        v0 += residual[(size_t)r * N + c];
                        if (c1ok) v1 += residual[(size_t)r * N + c + 1];
                    }
                    C[(size_t)r * N + c] = v0;
                    if (c1ok) C[(size_t)r * N + c + 1] = v1;
                }
            }
        }
    }
}

// ---------------- attention: one block per (q, head, batch) ----------------
__global__ void attention_kernel(const float* __restrict__ qkv,
                                 __half* __restrict__ ohi,
                                 __half* __restrict__ olo) {
    int q = blockIdx.x, h = blockIdx.y, b = blockIdx.z;
    int tid = threadIdx.x;
    __shared__ float sq[HDIM];
    __shared__ float ss[TT];
    __shared__ float red[256];

    const float* qptr = qkv + ((size_t)(b * TT + q)) * D3 + h * HDIM;
    if (tid < HDIM) sq[tid] = qptr[tid];
    __syncthreads();

    float lmax = -1e30f;
    for (int k = tid; k <= q; k += 256) {
        const float* kptr = qkv + ((size_t)(b * TT + k)) * D3 + DD + h * HDIM;
        float s = 0.f;
#pragma unroll
        for (int d = 0; d < HDIM; d++) s += sq[d] * kptr[d];
        s *= 0.125f;
        ss[k] = s;
        lmax = fmaxf(lmax, s);
    }
    red[tid] = lmax; __syncthreads();
    for (int o = 128; o > 0; o >>= 1) {
        if (tid < o) red[tid] = fmaxf(red[tid], red[tid + o]);
        __syncthreads();
    }
    float mx = red[0];
    __syncthreads();

    float lsum = 0.f;
    for (int k = tid; k <= q; k += 256) {
        float e = expf(ss[k] - mx);
        ss[k] = e;
        lsum += e;
    }
    red[tid] = lsum; __syncthreads();
    for (int o = 128; o > 0; o >>= 1) {
        if (tid < o) red[tid] += red[tid + o];
        __syncthreads();
    }
    float inv = 1.0f / red[0];

    if (tid < HDIM) {
        const float* vbase = qkv + (size_t)b * TT * D3 + 2 * DD + h * HDIM + tid;
        float acc = 0.f;
        for (int k = 0; k <= q; k++)
            acc += ss[k] * vbase[(size_t)k * D3];
        float v = acc * inv;
        __half hi, lo;
        split2h(v, hi, lo);
        size_t oi = ((size_t)(b * TT + q)) * DD + h * HDIM + tid;
        ohi[oi] = hi; olo[oi] = lo;
    }
}

// ---------------- launch ----------------
extern "C" void kernel_launch(void* const* d_in, const int* in_sizes, int n_in,
                              void* d_out, int out_size) {
    const int*   ids    = (const int*)  d_in[0];
    const float* wte    = (const float*)d_in[1];
    const float* wpe    = (const float*)d_in[2];
    const float* ln1_g  = (const float*)d_in[3];
    const float* ln1_b  = (const float*)d_in[4];
    const float* attn_w = (const float*)d_in[5];
    const float* attn_b = (const float*)d_in[6];
    const float* proj_w = (const float*)d_in[7];
    const float* proj_b = (const float*)d_in[8];
    const float* ln2_g  = (const float*)d_in[9];
    const float* ln2_b  = (const float*)d_in[10];
    const float* fc_w   = (const float*)d_in[11];
    const float* fc_b   = (const float*)d_in[12];
    const float* out_w  = (const float*)d_in[13];
    const float* out_b  = (const float*)d_in[14];
    const float* lnf_g  = (const float*)d_in[15];
    const float* lnf_b  = (const float*)d_in[16];
    float* logits = (float*)d_out;

    float *x, *qkv;
    __half *h_hi, *h_lo, *at_hi, *at_lo, *fc_hi, *fc_lo;
    __half *awT_hi, *awT_lo, *pwT_hi, *pwT_lo, *fwT_hi, *fwT_lo, *owT_hi, *owT_lo;
    __half *wte_h;
    cudaGetSymbolAddress((void**)&x,      g_x);
    cudaGetSymbolAddress((void**)&qkv,    g_qkv);
    cudaGetSymbolAddress((void**)&h_hi,   g_h_hi);
    cudaGetSymbolAddress((void**)&h_lo,   g_h_lo);
    cudaGetSymbolAddress((void**)&at_hi,  g_attn_hi);
    cudaGetSymbolAddress((void**)&at_lo,  g_attn_lo);
    cudaGetSymbolAddress((void**)&fc_hi,  g_fc_hi);
    cudaGetSymbolAddress((void**)&fc_lo,  g_fc_lo);
    cudaGetSymbolAddress((void**)&awT_hi, g_attnwT_hi);
    cudaGetSymbolAddress((void**)&awT_lo, g_attnwT_lo);
    cudaGetSymbolAddress((void**)&pwT_hi, g_projwT_hi);
    cudaGetSymbolAddress((void**)&pwT_lo, g_projwT_lo);
    cudaGetSymbolAddress((void**)&fwT_hi, g_fcwT_hi);
    cudaGetSymbolAddress((void**)&fwT_lo, g_fcwT_lo);
    cudaGetSymbolAddress((void**)&owT_hi, g_outwT_hi);
    cudaGetSymbolAddress((void**)&owT_lo, g_outwT_lo);
    cudaGetSymbolAddress((void**)&wte_h,  g_wte_h);

    const int SM3 = STAGES * 4 * MAT_BYTES;   // 122880
    const int SM1 = STAGES * 2 * MAT_BYTES;   // 61440
    cudaFuncSetAttribute(gemm_hl<3,0,0,0>, cudaFuncAttributeMaxDynamicSharedMemorySize, SM3);
    cudaFuncSetAttribute(gemm_hl<3,0,0,1>, cudaFuncAttributeMaxDynamicSharedMemorySize, SM3);
    cudaFuncSetAttribute(gemm_hl<3,1,1,0>, cudaFuncAttributeMaxDynamicSharedMemorySize, SM3);
    cudaFuncSetAttribute(gemm_hl<1,0,0,0>, cudaFuncAttributeMaxDynamicSharedMemorySize, SM1);

    dim3 tb(32, 8);
    const dim3 gQKV(D3 / BN, MM / BM), gPROJ(DD / BN, MM / BM),
               gFC(D4 / BN, MM / BM),  gOUT(DD / BN, MM / BM),
               gLM((VV + BN - 1) / BN, MM / BM);

    // Launch order arranged so ncu (-s 5 -c 1) profiles the 6th launch = qkv GEMM.
    embed_kernel<<<(MM * DD + 255) / 256, 256>>>(ids, wte, wpe, x);                     // 1
    layernorm_split_kernel<<<MM, 256>>>(x, ln1_g, ln1_b, h_hi, h_lo);                   // 2
    conv_transpose_kernel<<<dim3(D3 / 32, DD / 32, LL), tb>>>(attn_w, awT_hi, awT_lo, DD, D3); // 3
    conv_wte_kernel<<<(VV * DD + 255) / 256, 256>>>(wte, wte_h, VV * DD);               // 4
    conv_transpose_kernel<<<dim3(DD / 32, DD / 32, LL), tb>>>(proj_w, pwT_hi, pwT_lo, DD, DD); // 5
    gemm_hl<3,0,0,0><<<gQKV, 256, SM3>>>(                                               // 6 <- profiled
        h_hi, h_lo, awT_hi, awT_lo, attn_b, nullptr, qkv, nullptr, nullptr, D3, DD);
    attention_kernel<<<dim3(TT, HH, BB), 256>>>(qkv, at_hi, at_lo);                     // 7
    conv_transpose_kernel<<<dim3(D4 / 32, DD / 32, LL), tb>>>(fc_w, fwT_hi, fwT_lo, DD, D4);   // 8
    conv_transpose_kernel<<<dim3(DD / 32, D4 / 32, LL), tb>>>(out_w, owT_hi, owT_lo, D4, DD);  // 9

    for (int l = 0; l < LL; l++) {
        if (l > 0) {
            layernorm_split_kernel<<<MM, 256>>>(x, ln1_g + l * DD, ln1_b + l * DD, h_hi, h_lo);
            gemm_hl<3,0,0,0><<<gQKV, 256, SM3>>>(
                h_hi, h_lo, awT_hi + (size_t)l * D3 * DD, awT_lo + (size_t)l * D3 * DD,
                attn_b + (size_t)l * D3, nullptr, qkv, nullptr, nullptr, D3, DD);
            attention_kernel<<<dim3(TT, HH, BB), 256>>>(qkv, at_hi, at_lo);
        }

        gemm_hl<3,0,0,1><<<gPROJ, 256, SM3>>>(
            at_hi, at_lo, pwT_hi + (size_t)l * DD * DD, pwT_lo + (size_t)l * DD * DD,
            proj_b + (size_t)l * DD, x, x, nullptr, nullptr, DD, DD);

        layernorm_split_kernel<<<MM, 256>>>(x, ln2_g + l * DD, ln2_b + l * DD, h_hi, h_lo);

        gemm_hl<3,1,1,0><<<gFC, 256, SM3>>>(
            h_hi, h_lo, fwT_hi + (size_t)l * D4 * DD, fwT_lo + (size_t)l * D4 * DD,
            fc_b + (size_t)l * D4, nullptr, nullptr, fc_hi, fc_lo, D4, DD);

        gemm_hl<3,0,0,1><<<gOUT, 256, SM3>>>(
            fc_hi, fc_lo, owT_hi + (size_t)l * DD * D4, owT_lo + (size_t)l * DD * D4,
            out_b + (size_t)l * DD, x, x, nullptr, nullptr, DD, D4);
    }

    layernorm_split_kernel<<<MM, 256>>>(x, lnf_g, lnf_b, h_hi, h_lo);

    // lm_head: logits = h @ wte^T   (single-pass fp16)
    gemm_hl<1,0,0,0><<<gLM, 256, SM1>>>(
        h_hi, nullptr, wte_h, nullptr,
        nullptr, nullptr, logits, nullptr, nullptr, VV, DD);
}

// round 6
// speedup vs baseline: 1.1047x; 1.0479x over previous
#include <cuda_runtime.h>
#include <cuda_fp16.h>
#include <math.h>

// ---------------- problem constants ----------------
#define BB   2
#define TT   1024
#define DD   768
#define HH   12
#define HDIM 64
#define LL   4
#define VV   50257
#define MM   (BB*TT)      // 2048
#define D3   (3*DD)       // 2304
#define D4   (4*DD)       // 3072

// ---------------- GEMM config ----------------
#define BM 128
#define BN 128
#define BK 32
#define STAGES 3
#define ASTRIDE 40                          // fp16 elems per smem row (32 + 8 pad)
#define MAT_BYTES (128 * ASTRIDE * 2)       // 10240 B per matrix per stage

// ---------------- scratch (device globals; no allocations) ----------
__device__ float g_x   [MM * DD];
__device__ float g_qkv [MM * D3];

__device__ __align__(16) __half g_h_h   [MM * DD];   // LN output (single fp16)
__device__ __align__(16) __half g_attn_h[MM * DD];   // attention output
__device__ __align__(16) __half g_fc_h  [MM * D4];   // mlp hidden

// transposed weights [N][K], fp16 hi/lo (exact sum)
__device__ __align__(16) __half g_attnwT_hi[LL * D3 * DD];
__device__ __align__(16) __half g_attnwT_lo[LL * D3 * DD];
__device__ __align__(16) __half g_projwT_hi[LL * DD * DD];
__device__ __align__(16) __half g_projwT_lo[LL * DD * DD];
__device__ __align__(16) __half g_fcwT_hi  [LL * D4 * DD];
__device__ __align__(16) __half g_fcwT_lo  [LL * D4 * DD];
__device__ __align__(16) __half g_outwT_hi [LL * DD * D4];
__device__ __align__(16) __half g_outwT_lo [LL * DD * D4];
__device__ __align__(16) __half g_wte_h    [VV * DD];

// ---------------- helpers ----------------
__device__ __forceinline__ void split2h(float x, __half& hi, __half& lo) {
    hi = __float2half_rn(x);
    lo = __float2half_rn(x - __half2float(hi));
}

__device__ __forceinline__ void mma_f16(float* c, const unsigned* a, const unsigned* b) {
    asm volatile(
        "mma.sync.aligned.m16n8k16.row.col.f32.f16.f16.f32 "
        "{%0,%1,%2,%3}, {%4,%5,%6,%7}, {%8,%9}, {%0,%1,%2,%3};"
        : "+f"(c[0]), "+f"(c[1]), "+f"(c[2]), "+f"(c[3])
        : "r"(a[0]), "r"(a[1]), "r"(a[2]), "r"(a[3]), "r"(b[0]), "r"(b[1]));
}

#define LDSM_X4(r0, r1, r2, r3, addr) \
    asm volatile("ldmatrix.sync.aligned.m8n8.x4.shared.b16 {%0,%1,%2,%3}, [%4];" \
                 : "=r"(r0), "=r"(r1), "=r"(r2), "=r"(r3) : "r"(addr))

#define CP_ASYNC16(saddr, gaddr, sz) \
    asm volatile("cp.async.cg.shared.global [%0], [%1], 16, %2;" \
                 :: "r"(saddr), "l"(gaddr), "r"(sz) : "memory")
#define CP_COMMIT() asm volatile("cp.async.commit_group;" ::: "memory")
#define CP_WAIT1()  asm volatile("cp.async.wait_group 1;" ::: "memory")

// ---------------- conversion kernels ----------------
__global__ void conv_wte_kernel(const float* __restrict__ src,
                                __half* __restrict__ dst, int n4) {
    int i = blockIdx.x * blockDim.x + threadIdx.x;
    if (i >= n4) return;
    float4 v = reinterpret_cast<const float4*>(src)[i];
    __half2 a = __half2(__float2half_rn(v.x), __float2half_rn(v.y));
    __half2 b = __half2(__float2half_rn(v.z), __float2half_rn(v.w));
    reinterpret_cast<__half2*>(dst)[2 * i]     = a;
    reinterpret_cast<__half2*>(dst)[2 * i + 1] = b;
}

// batched transpose + split: src [l][K][N] fp32 -> dst [l][N][K] fp16 hi/lo
__global__ void conv_transpose_kernel(const float* __restrict__ src,
                                      __half* __restrict__ dhi,
                                      __half* __restrict__ dlo,
                                      int Kd, int Nd) {
    int l = blockIdx.z;
    src += (size_t)l * Kd * Nd;
    dhi += (size_t)l * Nd * Kd;
    dlo += (size_t)l * Nd * Kd;
    __shared__ float t[32][33];
    int n0 = blockIdx.x * 32, k0 = blockIdx.y * 32;
    int tx = threadIdx.x, ty = threadIdx.y;   // 32 x 8
#pragma unroll
    for (int i = 0; i < 4; i++) {
        int k = k0 + ty + i * 8, n = n0 + tx;
        if (k < Kd && n < Nd) t[ty + i * 8][tx] = src[(size_t)k * Nd + n];
    }
    __syncthreads();
#pragma unroll
    for (int i = 0; i < 4; i++) {
        int n = n0 + ty + i * 8, k = k0 + tx;
        if (n < Nd && k < Kd) {
            __half h, lo;
            split2h(t[tx][ty + i * 8], h, lo);
            dhi[(size_t)n * Kd + k] = h;
            dlo[(size_t)n * Kd + k] = lo;
        }
    }
}

// ---------------- embedding ----------------
__global__ void embed_kernel(const int* __restrict__ ids,
                             const float* __restrict__ wte,
                             const float* __restrict__ wpe,
                             float* __restrict__ x) {
    int idx = blockIdx.x * blockDim.x + threadIdx.x;
    if (idx >= MM * DD) return;
    int d  = idx % DD;
    int bt = idx / DD;
    int t  = bt % TT;
    x[idx] = wte[(size_t)ids[bt] * DD + d] + wpe[(size_t)t * DD + d];
}

// ---------------- layernorm: fp32 in -> fp16 out -------------
__global__ void layernorm_h_kernel(const float* __restrict__ x,
                                   const float* __restrict__ g,
                                   const float* __restrict__ b,
                                   __half* __restrict__ out) {
    int row = blockIdx.x;
    int tid = threadIdx.x;
    __shared__ float red[256];
    __shared__ float s_mu, s_rstd;
    const float* xr = x + (size_t)row * DD;

    float s = 0.f;
    for (int d = tid; d < DD; d += 256) s += xr[d];
    red[tid] = s; __syncthreads();
    for (int o = 128; o > 0; o >>= 1) {
        if (tid < o) red[tid] += red[tid + o];
        __syncthreads();
    }
    if (tid == 0) s_mu = red[0] / DD;
    __syncthreads();
    float mu = s_mu;

    float v = 0.f;
    for (int d = tid; d < DD; d += 256) { float t = xr[d] - mu; v += t * t; }
    red[tid] = v; __syncthreads();
    for (int o = 128; o > 0; o >>= 1) {
        if (tid < o) red[tid] += red[tid + o];
        __syncthreads();
    }
    if (tid == 0) s_rstd = rsqrtf(red[0] / DD + 1e-5f);
    __syncthreads();
    float rstd = s_rstd;

    for (int d = tid; d < DD; d += 256)
        out[(size_t)row * DD + d] =
            __float2half_rn(g[d] * (xr[d] - mu) * rstd + b[d]);
}

// ---------------- fp16 GEMM (mma.sync m16n8k16 + ldmatrix) ----------------
// TERMS==2: C = A.(Bhi+Blo)^T   (weights exact, activation eps 2^-12)
// TERMS==1: C = A.B^T           (single-pass fp16, lm-head)
// A[M,K], B[N,K] fp16 row-major. +bias (+gelu) (+residual / fp16-write).
// 256 threads / 8 warps; warp tile 64x32; 3-stage cp.async; 2 CTAs/SM.
template <int TERMS, int ACT, int WRITE_HALF, int HAS_RES>
__global__ void __launch_bounds__(256, 2)
gemm_h(const __half* __restrict__ A,
       const __half* __restrict__ Bhi, const __half* __restrict__ Blo,
       const float* __restrict__ bias, const float* __restrict__ residual,
       float* __restrict__ C, __half* __restrict__ Ch,
       int N, int K) {
    constexpr int NMAT = TERMS + 1;                 // A + B terms
    constexpr int STAGE_BYTES = NMAT * MAT_BYTES;
    constexpr unsigned A_OFF   = 0;
    constexpr unsigned BHI_OFF = MAT_BYTES;
    constexpr unsigned BLO_OFF = 2 * MAT_BYTES;

    extern __shared__ char sm[];
    const unsigned smb = (unsigned)__cvta_generic_to_shared(sm);

    const int tid  = threadIdx.x;
    const int lane = tid & 31;
    const int wid  = tid >> 5;
    const int wm   = (wid & 1) * 64;
    const int wn   = (wid >> 1) * 32;
    const int gp   = lane >> 2;
    const int tg   = lane & 3;
    const int row0 = blockIdx.y * BM;
    const int col0 = blockIdx.x * BN;
    const int nk   = K / BK;

    // ldmatrix lane mapping
    const int lrow  = lane & 15;
    const int lcol8 = (lane >> 4) * 8;

    // global loader mapping: thread -> one row, 16-elem half
    const int lr = tid >> 1;
    const int lc = (tid & 1) * 16;
    const size_t aoff = (size_t)(row0 + lr) * K + lc;
    const int nrow = col0 + lr;
    const unsigned bsz = (nrow < N) ? 16u : 0u;
    const size_t boff = (size_t)((nrow < N) ? nrow : 0) * K + lc;
    const unsigned s_row = (unsigned)((lr * ASTRIDE + lc) * 2);

    float acc[4][4][4];
#pragma unroll
    for (int a = 0; a < 4; a++)
#pragma unroll
        for (int b = 0; b < 4; b++)
#pragma unroll
            for (int c = 0; c < 4; c++) acc[a][b][c] = 0.f;

    auto load_stage = [&](int slot, int k0) {
        unsigned base = smb + slot * STAGE_BYTES;
        const char* ga  = (const char*)(A + aoff + k0);
        const char* gbh = (const char*)(Bhi + boff + k0);
        CP_ASYNC16(base + A_OFF + s_row,        ga,       16u);
        CP_ASYNC16(base + A_OFF + s_row + 16,   ga + 16,  16u);
        CP_ASYNC16(base + BHI_OFF + s_row,      gbh,      bsz);
        CP_ASYNC16(base + BHI_OFF + s_row + 16, gbh + 16, bsz);
        if (TERMS == 2) {
            const char* gbl = (const char*)(Blo + boff + k0);
            CP_ASYNC16(base + BLO_OFF + s_row,      gbl,      bsz);
            CP_ASYNC16(base + BLO_OFF + s_row + 16, gbl + 16, bsz);
        }
    };

#pragma unroll
    for (int p = 0; p < STAGES - 1; p++) {
        if (p < nk) load_stage(p, p * BK);
        CP_COMMIT();
    }

    for (int kt = 0; kt < nk; kt++) {
        int ldk = kt + STAGES - 1;
        if (ldk < nk) load_stage(ldk % STAGES, ldk * BK);
        CP_COMMIT();
        CP_WAIT1();
        __syncthreads();

        const unsigned st = smb + (kt % STAGES) * STAGE_BYTES;

#pragma unroll
        for (int ks = 0; ks < 2; ks++) {
            const int kb = ks * 16 + lcol8;
            unsigned ar[4][4], bh[4][2], bl[4][2];
#pragma unroll
            for (int mi = 0; mi < 4; mi++) {
                unsigned ad = st + A_OFF + ((wm + mi * 16 + lrow) * ASTRIDE + kb) * 2;
                LDSM_X4(ar[mi][0], ar[mi][1], ar[mi][2], ar[mi][3], ad);
            }
#pragma unroll
            for (int p = 0; p < 2; p++) {
                unsigned bd = st + BHI_OFF + ((wn + p * 16 + lrow) * ASTRIDE + kb) * 2;
                unsigned t0, t1, t2, t3;
                LDSM_X4(t0, t1, t2, t3, bd);
                bh[2 * p][0] = t0; bh[2 * p + 1][0] = t1;
                bh[2 * p][1] = t2; bh[2 * p + 1][1] = t3;
                if (TERMS == 2) {
                    unsigned bd2 = st + BLO_OFF + ((wn + p * 16 + lrow) * ASTRIDE + kb) * 2;
                    LDSM_X4(t0, t1, t2, t3, bd2);
                    bl[2 * p][0] = t0; bl[2 * p + 1][0] = t1;
                    bl[2 * p][1] = t2; bl[2 * p + 1][1] = t3;
                }
            }
#pragma unroll
            for (int mi = 0; mi < 4; mi++)
#pragma unroll
                for (int ni = 0; ni < 4; ni++) {
                    mma_f16(acc[mi][ni], ar[mi], bh[ni]);
                    if (TERMS == 2) mma_f16(acc[mi][ni], ar[mi], bl[ni]);
                }
        }
        __syncthreads();
    }

    // ---- epilogue ----
#pragma unroll
    for (int mi = 0; mi < 4; mi++) {
        int rb = row0 + wm + mi * 16 + gp;
#pragma unroll
        for (int ni = 0; ni < 4; ni++) {
            int c = col0 + wn + ni * 8 + tg * 2;
            if (c >= N) continue;
            bool c1ok = (c + 1 < N);
#pragma unroll
            for (int half = 0; half < 2; half++) {
                int r = rb + half * 8;
                float v0 = acc[mi][ni][half * 2 + 0];
                float v1 = acc[mi][ni][half * 2 + 1];
                if (bias) { v0 += bias[c]; if (c1ok) v1 += bias[c + 1]; }
                if (ACT) {
                    v0 = 0.5f * v0 * (1.0f + erff(v0 * 0.70710678118654752f));
                    v1 = 0.5f * v1 * (1.0f + erff(v1 * 0.70710678118654752f));
                }
                if (WRITE_HALF) {
                    *reinterpret_cast<__half2*>(&Ch[(size_t)r * N + c]) =
                        __half2(__float2half_rn(v0), __float2half_rn(v1));
                } else {
                    if (HAS_RES) {
                        v0 += residual[(size_t)r * N + c];
                        if (c1ok) v1 += residual[(size_t)r * N + c + 1];
                    }
                    C[(size_t)r * N + c] = v0;
                    if (c1ok) C[(size_t)r * N + c + 1] = v1;
                }
            }
        }
    }
}

// ---------------- attention: one block per (q, head, batch) ----------------
__global__ void attention_kernel(const float* __restrict__ qkv,
                                 __half* __restrict__ oh) {
    int q = blockIdx.x, h = blockIdx.y, b = blockIdx.z;
    int tid = threadIdx.x;
    __shared__ float sq[HDIM];
    __shared__ float ss[TT];
    __shared__ float red[256];

    const float* qptr = qkv + ((size_t)(b * TT + q)) * D3 + h * HDIM;
    if (tid < HDIM) sq[tid] = qptr[tid];
    __syncthreads();

    float lmax = -1e30f;
    for (int k = tid; k <= q; k += 256) {
        const float* kptr = qkv + ((size_t)(b * TT + k)) * D3 + DD + h * HDIM;
        float s = 0.f;
#pragma unroll
        for (int d = 0; d < HDIM; d++) s += sq[d] * kptr[d];
        s *= 0.125f;
        ss[k] = s;
        lmax = fmaxf(lmax, s);
    }
    red[tid] = lmax; __syncthreads();
    for (int o = 128; o > 0; o >>= 1) {
        if (tid < o) red[tid] = fmaxf(red[tid], red[tid + o]);
        __syncthreads();
    }
    float mx = red[0];
    __syncthreads();

    float lsum = 0.f;
    for (int k = tid; k <= q; k += 256) {
        float e = expf(ss[k] - mx);
        ss[k] = e;
        lsum += e;
    }
    red[tid] = lsum; __syncthreads();
    for (int o = 128; o > 0; o >>= 1) {
        if (tid < o) red[tid] += red[tid + o];
        __syncthreads();
    }
    float inv = 1.0f / red[0];

    if (tid < HDIM) {
        const float* vbase = qkv + (size_t)b * TT * D3 + 2 * DD + h * HDIM + tid;
        float acc = 0.f;
        for (int k = 0; k <= q; k++)
            acc += ss[k] * vbase[(size_t)k * D3];
        oh[((size_t)(b * TT + q)) * DD + h * HDIM + tid] = __float2half_rn(acc * inv);
    }
}

// ---------------- launch ----------------
extern "C" void kernel_launch(void* const* d_in, const int* in_sizes, int n_in,
                              void* d_out, int out_size) {
    const int*   ids    = (const int*)  d_in[0];
    const float* wte    = (const float*)d_in[1];
    const float* wpe    = (const float*)d_in[2];
    const float* ln1_g  = (const float*)d_in[3];
    const float* ln1_b  = (const float*)d_in[4];
    const float* attn_w = (const float*)d_in[5];
    const float* attn_b = (const float*)d_in[6];
    const float* proj_w = (const float*)d_in[7];
    const float* proj_b = (const float*)d_in[8];
    const float* ln2_g  = (const float*)d_in[9];
    const float* ln2_b  = (const float*)d_in[10];
    const float* fc_w   = (const float*)d_in[11];
    const float* fc_b   = (const float*)d_in[12];
    const float* out_w  = (const float*)d_in[13];
    const float* out_b  = (const float*)d_in[14];
    const float* lnf_g  = (const float*)d_in[15];
    const float* lnf_b  = (const float*)d_in[16];
    float* logits = (float*)d_out;

    float *x, *qkv;
    __half *h_h, *at_h, *fc_h;
    __half *awT_hi, *awT_lo, *pwT_hi, *pwT_lo, *fwT_hi, *fwT_lo, *owT_hi, *owT_lo, *wte_h;
    cudaGetSymbolAddress((void**)&x,      g_x);
    cudaGetSymbolAddress((void**)&qkv,    g_qkv);
    cudaGetSymbolAddress((void**)&h_h,    g_h_h);
    cudaGetSymbolAddress((void**)&at_h,   g_attn_h);
    cudaGetSymbolAddress((void**)&fc_h,   g_fc_h);
    cudaGetSymbolAddress((void**)&awT_hi, g_attnwT_hi);
    cudaGetSymbolAddress((void**)&awT_lo, g_attnwT_lo);
    cudaGetSymbolAddress((void**)&pwT_hi, g_projwT_hi);
    cudaGetSymbolAddress((void**)&pwT_lo, g_projwT_lo);
    cudaGetSymbolAddress((void**)&fwT_hi, g_fcwT_hi);
    cudaGetSymbolAddress((void**)&fwT_lo, g_fcwT_lo);
    cudaGetSymbolAddress((void**)&owT_hi, g_outwT_hi);
    cudaGetSymbolAddress((void**)&owT_lo, g_outwT_lo);
    cudaGetSymbolAddress((void**)&wte_h,  g_wte_h);

    const int SM2 = STAGES * 3 * MAT_BYTES;   // 92160
    const int SM1 = STAGES * 2 * MAT_BYTES;   // 61440
    cudaFuncSetAttribute(gemm_h<2,0,0,0>, cudaFuncAttributeMaxDynamicSharedMemorySize, SM2);
    cudaFuncSetAttribute(gemm_h<2,0,0,1>, cudaFuncAttributeMaxDynamicSharedMemorySize, SM2);
    cudaFuncSetAttribute(gemm_h<2,1,1,0>, cudaFuncAttributeMaxDynamicSharedMemorySize, SM2);
    cudaFuncSetAttribute(gemm_h<1,0,0,0>, cudaFuncAttributeMaxDynamicSharedMemorySize, SM1);

    dim3 tb(32, 8);
    const dim3 gQKV(D3 / BN, MM / BM), gPROJ(DD / BN, MM / BM),
               gFC(D4 / BN, MM / BM),  gOUT(DD / BN, MM / BM),
               gLM((VV + BN - 1) / BN, MM / BM);

    // Launch order: ncu captures the 4th launch -> make it the QKV GEMM.
    embed_kernel<<<(MM * DD + 255) / 256, 256>>>(ids, wte, wpe, x);                          // 1
    conv_transpose_kernel<<<dim3(D3 / 32, DD / 32, LL), tb>>>(attn_w, awT_hi, awT_lo, DD, D3); // 2
    layernorm_h_kernel<<<MM, 256>>>(x, ln1_g, ln1_b, h_h);                                   // 3
    gemm_h<2,0,0,0><<<gQKV, 256, SM2>>>(                                                     // 4 <- profiled
        h_h, awT_hi, awT_lo, attn_b, nullptr, qkv, nullptr, D3, DD);
    attention_kernel<<<dim3(TT, HH, BB), 256>>>(qkv, at_h);                                  // 5
    conv_transpose_kernel<<<dim3(DD / 32, DD / 32, LL), tb>>>(proj_w, pwT_hi, pwT_lo, DD, DD); // 6
    conv_transpose_kernel<<<dim3(D4 / 32, DD / 32, LL), tb>>>(fc_w, fwT_hi, fwT_lo, DD, D4);   // 7
    conv_transpose_kernel<<<dim3(DD / 32, D4 / 32, LL), tb>>>(out_w, owT_hi, owT_lo, D4, DD);  // 8
    conv_wte_kernel<<<(VV * DD / 4 + 255) / 256, 256>>>(wte, wte_h, VV * DD / 4);            // 9

    for (int l = 0; l < LL; l++) {
        if (l > 0) {
            layernorm_h_kernel<<<MM, 256>>>(x, ln1_g + l * DD, ln1_b + l * DD, h_h);
            gemm_h<2,0,0,0><<<gQKV, 256, SM2>>>(
                h_h, awT_hi + (size_t)l * D3 * DD, awT_lo + (size_t)l * D3 * DD,
                attn_b + (size_t)l * D3, nullptr, qkv, nullptr, D3, DD);
            attention_kernel<<<dim3(TT, HH, BB), 256>>>(qkv, at_h);
        }

        gemm_h<2,0,0,1><<<gPROJ, 256, SM2>>>(
            at_h, pwT_hi + (size_t)l * DD * DD, pwT_lo + (size_t)l * DD * DD,
            proj_b + (size_t)l * DD, x, x, nullptr, DD, DD);

        layernorm_h_kernel<<<MM, 256>>>(x, ln2_g + l * DD, ln2_b + l * DD, h_h);

        gemm_h<2,1,1,0><<<gFC, 256, SM2>>>(
            h_h, fwT_hi + (size_t)l * D4 * DD, fwT_lo + (size_t)l * D4 * DD,
            fc_b + (size_t)l * D4, nullptr, nullptr, fc_h, D4, DD);

        gemm_h<2,0,0,1><<<gOUT, 256, SM2>>>(
            fc_h, owT_hi + (size_t)l * DD * D4, owT_lo + (size_t)l * DD * D4,
            out_b + (size_t)l * DD, x, x, nullptr, DD, D4);
    }

    layernorm_h_kernel<<<MM, 256>>>(x, lnf_g, lnf_b, h_h);

    // lm_head: logits = h @ wte^T   (single-pass fp16)
    gemm_h<1,0,0,0><<<gLM, 256, SM1>>>(
        h_h, wte_h, nullptr, nullptr, nullptr, logits, nullptr, VV, DD);
}

// round 8
// speedup vs baseline: 3.8551x; 3.4898x over previous
#include <cuda_runtime.h>
#include <cuda_fp16.h>
#include <math.h>

// ---------------- problem constants ----------------
#define BB   2
#define TT   1024
#define DD   768
#define HH   12
#define HDIM 64
#define LL   4
#define VV   50257
#define MM   (BB*TT)      // 2048
#define D3   (3*DD)       // 2304
#define D4   (4*DD)       // 3072

// ---------------- GEMM config ----------------
#define BM 128
#define BN 128
#define BK 32
#define STAGES 3
#define ASTRIDE 40
#define MAT_BYTES (128 * ASTRIDE * 2)

// ---------------- attention config ----------------
#define AQ 64                 // queries per block
#define AK 64                 // keys per tile
#define QS 68                 // floats per smem row (64 + 4 pad, 16B-aligned)
// smem floats: sQ[64*68] sK[64*68] sV[64*68] sS[64*68] sScale[64]
#define ATT_SMEM ((4 * 64 * QS + 64) * 4)

// ---------------- scratch ----------------
__device__ float g_x   [MM * DD];
__device__ float g_qkv [MM * D3];

__device__ __align__(16) __half g_h_h   [MM * DD];
__device__ __align__(16) __half g_attn_h[MM * DD];
__device__ __align__(16) __half g_fc_h  [MM * D4];

__device__ __align__(16) __half g_attnwT_hi[LL * D3 * DD];
__device__ __align__(16) __half g_attnwT_lo[LL * D3 * DD];
__device__ __align__(16) __half g_projwT_hi[LL * DD * DD];
__device__ __align__(16) __half g_projwT_lo[LL * DD * DD];
__device__ __align__(16) __half g_fcwT_hi  [LL * D4 * DD];
__device__ __align__(16) __half g_fcwT_lo  [LL * D4 * DD];
__device__ __align__(16) __half g_outwT_hi [LL * DD * D4];
__device__ __align__(16) __half g_outwT_lo [LL * DD * D4];
__device__ __align__(16) __half g_wte_h    [VV * DD];

// ---------------- helpers ----------------
__device__ __forceinline__ void split2h(float x, __half& hi, __half& lo) {
    hi = __float2half_rn(x);
    lo = __float2half_rn(x - __half2float(hi));
}

__device__ __forceinline__ void mma_f16(float* c, const unsigned* a, const unsigned* b) {
    asm volatile(
        "mma.sync.aligned.m16n8k16.row.col.f32.f16.f16.f32 "
        "{%0,%1,%2,%3}, {%4,%5,%6,%7}, {%8,%9}, {%0,%1,%2,%3};"
        : "+f"(c[0]), "+f"(c[1]), "+f"(c[2]), "+f"(c[3])
        : "r"(a[0]), "r"(a[1]), "r"(a[2]), "r"(a[3]), "r"(b[0]), "r"(b[1]));
}

#define LDSM_X4(r0, r1, r2, r3, addr) \
    asm volatile("ldmatrix.sync.aligned.m8n8.x4.shared.b16 {%0,%1,%2,%3}, [%4];" \
                 : "=r"(r0), "=r"(r1), "=r"(r2), "=r"(r3) : "r"(addr))

#define CP_ASYNC16(saddr, gaddr, sz) \
    asm volatile("cp.async.cg.shared.global [%0], [%1], 16, %2;" \
                 :: "r"(saddr), "l"(gaddr), "r"(sz) : "memory")
#define CP_COMMIT() asm volatile("cp.async.commit_group;" ::: "memory")
#define CP_WAIT1()  asm volatile("cp.async.wait_group 1;" ::: "memory")

// ---------------- conversion kernels ----------------
__global__ void conv_wte_kernel(const float* __restrict__ src,
                                __half* __restrict__ dst, int n4) {
    int i = blockIdx.x * blockDim.x + threadIdx.x;
    if (i >= n4) return;
    float4 v = reinterpret_cast<const float4*>(src)[i];
    reinterpret_cast<__half2*>(dst)[2 * i]     = __half2(__float2half_rn(v.x), __float2half_rn(v.y));
    reinterpret_cast<__half2*>(dst)[2 * i + 1] = __half2(__float2half_rn(v.z), __float2half_rn(v.w));
}

__global__ void conv_transpose_kernel(const float* __restrict__ src,
                                      __half* __restrict__ dhi,
                                      __half* __restrict__ dlo,
                                      int Kd, int Nd) {
    int l = blockIdx.z;
    src += (size_t)l * Kd * Nd;
    dhi += (size_t)l * Nd * Kd;
    dlo += (size_t)l * Nd * Kd;
    __shared__ float t[32][33];
    int n0 = blockIdx.x * 32, k0 = blockIdx.y * 32;
    int tx = threadIdx.x, ty = threadIdx.y;
#pragma unroll
    for (int i = 0; i < 4; i++) {
        int k = k0 + ty + i * 8, n = n0 + tx;
        if (k < Kd && n < Nd) t[ty + i * 8][tx] = src[(size_t)k * Nd + n];
    }
    __syncthreads();
#pragma unroll
    for (int i = 0; i < 4; i++) {
        int n = n0 + ty + i * 8, k = k0 + tx;
        if (n < Nd && k < Kd) {
            __half h, lo;
            split2h(t[tx][ty + i * 8], h, lo);
            dhi[(size_t)n * Kd + k] = h;
            dlo[(size_t)n * Kd + k] = lo;
        }
    }
}

// ---------------- fused embed + layernorm(ln1 of layer 0) ----------------
__global__ void embed_ln_kernel(const int* __restrict__ ids,
                                const float* __restrict__ wte,
                                const float* __restrict__ wpe,
                                const float* __restrict__ g,
                                const float* __restrict__ b,
                                float* __restrict__ x,
                                __half* __restrict__ out) {
    int row = blockIdx.x;             // 0..MM-1
    int tid = threadIdx.x;            // 256
    int t = row % TT;
    __shared__ float e[DD];
    __shared__ float red[256];
    __shared__ float s_mu, s_rstd;
    const float* wt = wte + (size_t)ids[row] * DD;
    const float* wp = wpe + (size_t)t * DD;

    float s = 0.f;
    for (int d = tid; d < DD; d += 256) {
        float v = wt[d] + wp[d];
        e[d] = v;
        x[(size_t)row * DD + d] = v;
        s += v;
    }
    red[tid] = s; __syncthreads();
    for (int o = 128; o > 0; o >>= 1) {
        if (tid < o) red[tid] += red[tid + o];
        __syncthreads();
    }
    if (tid == 0) s_mu = red[0] / DD;
    __syncthreads();
    float mu = s_mu;

    float v = 0.f;
    for (int d = tid; d < DD; d += 256) { float t2 = e[d] - mu; v += t2 * t2; }
    red[tid] = v; __syncthreads();
    for (int o = 128; o > 0; o >>= 1) {
        if (tid < o) red[tid] += red[tid + o];
        __syncthreads();
    }
    if (tid == 0) s_rstd = rsqrtf(red[0] / DD + 1e-5f);
    __syncthreads();
    float rstd = s_rstd;

    for (int d = tid; d < DD; d += 256)
        out[(size_t)row * DD + d] = __float2half_rn(g[d] * (e[d] - mu) * rstd + b[d]);
}

// ---------------- layernorm: fp32 in -> fp16 out -------------
__global__ void layernorm_h_kernel(const float* __restrict__ x,
                                   const float* __restrict__ g,
                                   const float* __restrict__ b,
                                   __half* __restrict__ out) {
    int row = blockIdx.x;
    int tid = threadIdx.x;
    __shared__ float red[256];
    __shared__ float s_mu, s_rstd;
    const float* xr = x + (size_t)row * DD;

    float s = 0.f;
    for (int d = tid; d < DD; d += 256) s += xr[d];
    red[tid] = s; __syncthreads();
    for (int o = 128; o > 0; o >>= 1) {
        if (tid < o) red[tid] += red[tid + o];
        __syncthreads();
    }
    if (tid == 0) s_mu = red[0] / DD;
    __syncthreads();
    float mu = s_mu;

    float v = 0.f;
    for (int d = tid; d < DD; d += 256) { float t = xr[d] - mu; v += t * t; }
    red[tid] = v; __syncthreads();
    for (int o = 128; o > 0; o >>= 1) {
        if (tid < o) red[tid] += red[tid + o];
        __syncthreads();
    }
    if (tid == 0) s_rstd = rsqrtf(red[0] / DD + 1e-5f);
    __syncthreads();
    float rstd = s_rstd;

    for (int d = tid; d < DD; d += 256)
        out[(size_t)row * DD + d] = __float2half_rn(g[d] * (xr[d] - mu) * rstd + b[d]);
}

// ---------------- flash attention (tiled, fp32, online softmax) ------------
// grid (TT/AQ, HH, BB), 256 threads.
// Each block: 64 queries of one (b,h). K/V staged in smem 64 keys at a time.
// Thread layout: tq = tid>>4 (4-query group), tx = tid&15
//   scores: thread computes 4q x 4k (k = tx + 16j), micro-tiled from smem
//   PV:     thread accumulates 4q x 4d (d = tx*4..+3)
// Online softmax state (m, l) held by threads tid<64 (one per query).
__global__ void __launch_bounds__(256, 2)
flash_attn_kernel(const float* __restrict__ qkv, __half* __restrict__ oh) {
    extern __shared__ float sa[];
    float* sQ = sa;                    // 64 x QS
    float* sK = sa + 64 * QS;
    float* sV = sa + 2 * 64 * QS;
    float* sS = sa + 3 * 64 * QS;      // 64 x QS (scores/probs)
    float* sScale = sa + 4 * 64 * QS;  // 64

    const int qt = gridDim.x - 1 - blockIdx.x;   // heavy tiles first
    const int h  = blockIdx.y;
    const int b  = blockIdx.z;
    const int tid = threadIdx.x;
    const int tq = tid >> 4;
    const int tx = tid & 15;

    const size_t bh_base = (size_t)b * TT * D3 + h * HDIM;

    // load Q tile (64 rows x 64 floats), coalesced f4
    {
        const float4* gq;
#pragma unroll
        for (int i = 0; i < 4; i++) {
            int idx = tid + 256 * i;           // 0..1023
            int r = idx >> 4, f4 = idx & 15;
            gq = reinterpret_cast<const float4*>(qkv + bh_base + (size_t)(qt * AQ + r) * D3);
            reinterpret_cast<float4*>(sQ)[r * (QS / 4) + f4] = gq[f4];
        }
    }

    float m = -1e30f, l = 0.f;          // only meaningful for tid<64
    float O[4][4];
#pragma unroll
    for (int i = 0; i < 4; i++)
#pragma unroll
        for (int j = 0; j < 4; j++) O[i][j] = 0.f;

    const int ntiles = qt + 1;
    for (int kt = 0; kt < ntiles; kt++) {
        __syncthreads();   // previous tile's PV reads done before overwrite
        // load K and V tiles
#pragma unroll
        for (int i = 0; i < 4; i++) {
            int idx = tid + 256 * i;
            int r = idx >> 4, f4 = idx & 15;
            size_t grow = bh_base + (size_t)(kt * AK + r) * D3;
            reinterpret_cast<float4*>(sK)[r * (QS / 4) + f4] =
                reinterpret_cast<const float4*>(qkv + grow + DD)[f4];
            reinterpret_cast<float4*>(sV)[r * (QS / 4) + f4] =
                reinterpret_cast<const float4*>(qkv + grow + 2 * DD)[f4];
        }
        __syncthreads();

        // ---- scores: 4q x 4k per thread ----
        {
            float acc[4][4];
#pragma unroll
            for (int i = 0; i < 4; i++)
#pragma unroll
                for (int j = 0; j < 4; j++) acc[i][j] = 0.f;
#pragma unroll
            for (int d4 = 0; d4 < 16; d4++) {
                float4 qv[4], kv[4];
#pragma unroll
                for (int i = 0; i < 4; i++)
                    qv[i] = reinterpret_cast<const float4*>(sQ)[(tq * 4 + i) * (QS / 4) + d4];
#pragma unroll
                for (int j = 0; j < 4; j++)
                    kv[j] = reinterpret_cast<const float4*>(sK)[(tx + 16 * j) * (QS / 4) + d4];
#pragma unroll
                for (int i = 0; i < 4; i++)
#pragma unroll
                    for (int j = 0; j < 4; j++)
                        acc[i][j] += qv[i].x * kv[j].x + qv[i].y * kv[j].y
                                   + qv[i].z * kv[j].z + qv[i].w * kv[j].w;
            }
#pragma unroll
            for (int i = 0; i < 4; i++) {
                int qg = qt * AQ + tq * 4 + i;
#pragma unroll
                for (int j = 0; j < 4; j++) {
                    int kg = kt * AK + tx + 16 * j;
                    float s = acc[i][j] * 0.125f;
                    if (kg > qg) s = -1e30f;
                    sS[(tq * 4 + i) * QS + tx + 16 * j] = s;
                }
            }
        }
        __syncthreads();

        // ---- softmax update (one thread per query) ----
        if (tid < AQ) {
            float* srow = sS + tid * QS;
            float mt = m;
#pragma unroll 8
            for (int k = 0; k < AK; k++) mt = fmaxf(mt, srow[k]);
            float sc = expf(m - mt);
            float ls = 0.f;
#pragma unroll 8
            for (int k = 0; k < AK; k++) {
                float p = expf(srow[k] - mt);
                srow[k] = p;
                ls += p;
            }
            l = l * sc + ls;
            m = mt;
            sScale[tid] = sc;
        }
        __syncthreads();

        // ---- PV accumulate: 4q x 4d per thread ----
        {
            float sc0 = sScale[tq * 4 + 0], sc1 = sScale[tq * 4 + 1];
            float sc2 = sScale[tq * 4 + 2], sc3 = sScale[tq * 4 + 3];
#pragma unroll
            for (int j = 0; j < 4; j++) {
                O[0][j] *= sc0; O[1][j] *= sc1; O[2][j] *= sc2; O[3][j] *= sc3;
            }
#pragma unroll
            for (int k4 = 0; k4 < 16; k4++) {
                float4 p[4], v[4];
#pragma unroll
                for (int i = 0; i < 4; i++)
                    p[i] = reinterpret_cast<const float4*>(sS)[(tq * 4 + i) * (QS / 4) + k4];
#pragma unroll
                for (int jj = 0; jj < 4; jj++)
                    v[jj] = reinterpret_cast<const float4*>(sV)[(k4 * 4 + jj) * (QS / 4) + tx];
#pragma unroll
                for (int i = 0; i < 4; i++) {
                    O[i][0] += p[i].x * v[0].x + p[i].y * v[1].x + p[i].z * v[2].x + p[i].w * v[3].x;
                    O[i][1] += p[i].x * v[0].y + p[i].y * v[1].y + p[i].z * v[2].y + p[i].w * v[3].y;
                    O[i][2] += p[i].x * v[0].z + p[i].y * v[1].z + p[i].z * v[2].z + p[i].w * v[3].z;
                    O[i][3] += p[i].x * v[0].w + p[i].y * v[1].w + p[i].z * v[2].w + p[i].w * v[3].w;
                }
            }
        }
    }

    __syncthreads();
    if (tid < AQ) sScale[tid] = 1.0f / l;
    __syncthreads();

#pragma unroll
    for (int i = 0; i < 4; i++) {
        int q = tq * 4 + i;
        float inv = sScale[q];
        int qg = qt * AQ + q;
        __half* orow = oh + (size_t)(b * TT + qg) * DD + h * HDIM + tx * 4;
        *reinterpret_cast<__half2*>(orow) =
            __half2(__float2half_rn(O[i][0] * inv), __float2half_rn(O[i][1] * inv));
        *reinterpret_cast<__half2*>(orow + 2) =
            __half2(__float2half_rn(O[i][2] * inv), __float2half_rn(O[i][3] * inv));
    }
}

// ---------------- fp16 GEMM (mma.sync m16n8k16 + ldmatrix) ----------------
template <int TERMS, int ACT, int WRITE_HALF, int HAS_RES>
__global__ void __launch_bounds__(256, 2)
gemm_h(const __half* __restrict__ A,
       const __half* __restrict__ Bhi, const __half* __restrict__ Blo,
       const float* __restrict__ bias, const float* __restrict__ residual,
       float* __restrict__ C, __half* __restrict__ Ch,
       int N, int K) {
    constexpr int NMAT = TERMS + 1;
    constexpr int STAGE_BYTES = NMAT * MAT_BYTES;
    constexpr unsigned A_OFF   = 0;
    constexpr unsigned BHI_OFF = MAT_BYTES;
    constexpr unsigned BLO_OFF = 2 * MAT_BYTES;

    extern __shared__ char sm[];
    const unsigned smb = (unsigned)__cvta_generic_to_shared(sm);

    const int tid  = threadIdx.x;
    const int lane = tid & 31;
    const int wid  = tid >> 5;
    const int wm   = (wid & 1) * 64;
    const int wn   = (wid >> 1) * 32;
    const int gp   = lane >> 2;
    const int tg   = lane & 3;
    const int row0 = blockIdx.y * BM;
    const int col0 = blockIdx.x * BN;
    const int nk   = K / BK;

    const int lrow  = lane & 15;
    const int lcol8 = (lane >> 4) * 8;

    const int lr = tid >> 1;
    const int lc = (tid & 1) * 16;
    const size_t aoff = (size_t)(row0 + lr) * K + lc;
    const int nrow = col0 + lr;
    const unsigned bsz = (nrow < N) ? 16u : 0u;
    const size_t boff = (size_t)((nrow < N) ? nrow : 0) * K + lc;
    const unsigned s_row = (unsigned)((lr * ASTRIDE + lc) * 2);

    float acc[4][4][4];
#pragma unroll
    for (int a = 0; a < 4; a++)
#pragma unroll
        for (int b = 0; b < 4; b++)
#pragma unroll
            for (int c = 0; c < 4; c++) acc[a][b][c] = 0.f;

    auto load_stage = [&](int slot, int k0) {
        unsigned base = smb + slot * STAGE_BYTES;
        const char* ga  = (const char*)(A + aoff + k0);
        const char* gbh = (const char*)(Bhi + boff + k0);
        CP_ASYNC16(base + A_OFF + s_row,        ga,       16u);
        CP_ASYNC16(base + A_OFF + s_row + 16,   ga + 16,  16u);
        CP_ASYNC16(base + BHI_OFF + s_row,      gbh,      bsz);
        CP_ASYNC16(base + BHI_OFF + s_row + 16, gbh + 16, bsz);
        if (TERMS == 2) {
            const char* gbl = (const char*)(Blo + boff + k0);
            CP_ASYNC16(base + BLO_OFF + s_row,      gbl,      bsz);
            CP_ASYNC16(base + BLO_OFF + s_row + 16, gbl + 16, bsz);
        }
    };

#pragma unroll
    for (int p = 0; p < STAGES - 1; p++) {
        if (p < nk) load_stage(p, p * BK);
        CP_COMMIT();
    }

    for (int kt = 0; kt < nk; kt++) {
        int ldk = kt + STAGES - 1;
        if (ldk < nk) load_stage(ldk % STAGES, ldk * BK);
        CP_COMMIT();
        CP_WAIT1();
        __syncthreads();

        const unsigned st = smb + (kt % STAGES) * STAGE_BYTES;

#pragma unroll
        for (int ks = 0; ks < 2; ks++) {
            const int kb = ks * 16 + lcol8;
            unsigned ar[4][4], bh[4][2], bl[4][2];
#pragma unroll
            for (int mi = 0; mi < 4; mi++) {
                unsigned ad = st + A_OFF + ((wm + mi * 16 + lrow) * ASTRIDE + kb) * 2;
                LDSM_X4(ar[mi][0], ar[mi][1], ar[mi][2], ar[mi][3], ad);
            }
#pragma unroll
            for (int p = 0; p < 2; p++) {
                unsigned bd = st + BHI_OFF + ((wn + p * 16 + lrow) * ASTRIDE + kb) * 2;
                unsigned t0, t1, t2, t3;
                LDSM_X4(t0, t1, t2, t3, bd);
                bh[2 * p][0] = t0; bh[2 * p + 1][0] = t1;
                bh[2 * p][1] = t2; bh[2 * p + 1][1] = t3;
                if (TERMS == 2) {
                    unsigned bd2 = st + BLO_OFF + ((wn + p * 16 + lrow) * ASTRIDE + kb) * 2;
                    LDSM_X4(t0, t1, t2, t3, bd2);
                    bl[2 * p][0] = t0; bl[2 * p + 1][0] = t1;
                    bl[2 * p][1] = t2; bl[2 * p + 1][1] = t3;
                }
            }
#pragma unroll
            for (int mi = 0; mi < 4; mi++)
#pragma unroll
                for (int ni = 0; ni < 4; ni++) {
                    mma_f16(acc[mi][ni], ar[mi], bh[ni]);
                    if (TERMS == 2) mma_f16(acc[mi][ni], ar[mi], bl[ni]);
                }
        }
        __syncthreads();
    }

#pragma unroll
    for (int mi = 0; mi < 4; mi++) {
        int rb = row0 + wm + mi * 16 + gp;
#pragma unroll
        for (int ni = 0; ni < 4; ni++) {
            int c = col0 + wn + ni * 8 + tg * 2;
            if (c >= N) continue;
            bool c1ok = (c + 1 < N);
#pragma unroll
            for (int half = 0; half < 2; half++) {
                int r = rb + half * 8;
                float v0 = acc[mi][ni][half * 2 + 0];
                float v1 = acc[mi][ni][half * 2 + 1];
                if (bias) { v0 += bias[c]; if (c1ok) v1 += bias[c + 1]; }
                if (ACT) {
                    v0 = 0.5f * v0 * (1.0f + erff(v0 * 0.70710678118654752f));
                    v1 = 0.5f * v1 * (1.0f + erff(v1 * 0.70710678118654752f));
                }
                if (WRITE_HALF) {
                    *reinterpret_cast<__half2*>(&Ch[(size_t)r * N + c]) =
                        __half2(__float2half_rn(v0), __float2half_rn(v1));
                } else {
                    if (HAS_RES) {
                        v0 += residual[(size_t)r * N + c];
                        if (c1ok) v1 += residual[(size_t)r * N + c + 1];
                    }
                    C[(size_t)r * N + c] = v0;
                    if (c1ok) C[(size_t)r * N + c + 1] = v1;
                }
            }
        }
    }
}

// ---------------- launch ----------------
extern "C" void kernel_launch(void* const* d_in, const int* in_sizes, int n_in,
                              void* d_out, int out_size) {
    const int*   ids    = (const int*)  d_in[0];
    const float* wte    = (const float*)d_in[1];
    const float* wpe    = (const float*)d_in[2];
    const float* ln1_g  = (const float*)d_in[3];
    const float* ln1_b  = (const float*)d_in[4];
    const float* attn_w = (const float*)d_in[5];
    const float* attn_b = (const float*)d_in[6];
    const float* proj_w = (const float*)d_in[7];
    const float* proj_b = (const float*)d_in[8];
    const float* ln2_g  = (const float*)d_in[9];
    const float* ln2_b  = (const float*)d_in[10];
    const float* fc_w   = (const float*)d_in[11];
    const float* fc_b   = (const float*)d_in[12];
    const float* out_w  = (const float*)d_in[13];
    const float* out_b  = (const float*)d_in[14];
    const float* lnf_g  = (const float*)d_in[15];
    const float* lnf_b  = (const float*)d_in[16];
    float* logits = (float*)d_out;

    float *x, *qkv;
    __half *h_h, *at_h, *fc_h;
    __half *awT_hi, *awT_lo, *pwT_hi, *pwT_lo, *fwT_hi, *fwT_lo, *owT_hi, *owT_lo, *wte_h;
    cudaGetSymbolAddress((void**)&x,      g_x);
    cudaGetSymbolAddress((void**)&qkv,    g_qkv);
    cudaGetSymbolAddress((void**)&h_h,    g_h_h);
    cudaGetSymbolAddress((void**)&at_h,   g_attn_h);
    cudaGetSymbolAddress((void**)&fc_h,   g_fc_h);
    cudaGetSymbolAddress((void**)&awT_hi, g_attnwT_hi);
    cudaGetSymbolAddress((void**)&awT_lo, g_attnwT_lo);
    cudaGetSymbolAddress((void**)&pwT_hi, g_projwT_hi);
    cudaGetSymbolAddress((void**)&pwT_lo, g_projwT_lo);
    cudaGetSymbolAddress((void**)&fwT_hi, g_fcwT_hi);
    cudaGetSymbolAddress((void**)&fwT_lo, g_fcwT_lo);
    cudaGetSymbolAddress((void**)&owT_hi, g_outwT_hi);
    cudaGetSymbolAddress((void**)&owT_lo, g_outwT_lo);
    cudaGetSymbolAddress((void**)&wte_h,  g_wte_h);

    const int SM2 = STAGES * 3 * MAT_BYTES;
    const int SM1 = STAGES * 2 * MAT_BYTES;
    cudaFuncSetAttribute(gemm_h<2,0,0,0>, cudaFuncAttributeMaxDynamicSharedMemorySize, SM2);
    cudaFuncSetAttribute(gemm_h<2,0,0,1>, cudaFuncAttributeMaxDynamicSharedMemorySize, SM2);
    cudaFuncSetAttribute(gemm_h<2,1,1,0>, cudaFuncAttributeMaxDynamicSharedMemorySize, SM2);
    cudaFuncSetAttribute(gemm_h<1,0,0,0>, cudaFuncAttributeMaxDynamicSharedMemorySize, SM1);
    cudaFuncSetAttribute(flash_attn_kernel, cudaFuncAttributeMaxDynamicSharedMemorySize, ATT_SMEM);

    dim3 tb(32, 8);
    const dim3 gQKV(D3 / BN, MM / BM), gPROJ(DD / BN, MM / BM),
               gFC(D4 / BN, MM / BM),  gOUT(DD / BN, MM / BM),
               gLM((VV + BN - 1) / BN, MM / BM),
               gATT(TT / AQ, HH, BB);

    // order: ncu (-s 5 -c 1) captures the 4th launch -> flash_attn
    conv_transpose_kernel<<<dim3(D3 / 32, DD / 32, LL), tb>>>(attn_w, awT_hi, awT_lo, DD, D3); // 1
    embed_ln_kernel<<<MM, 256>>>(ids, wte, wpe, ln1_g, ln1_b, x, h_h);                         // 2
    gemm_h<2,0,0,0><<<gQKV, 256, SM2>>>(                                                       // 3
        h_h, awT_hi, awT_lo, attn_b, nullptr, qkv, nullptr, D3, DD);
    flash_attn_kernel<<<gATT, 256, ATT_SMEM>>>(qkv, at_h);                                     // 4 <- profiled
    conv_transpose_kernel<<<dim3(DD / 32, DD / 32, LL), tb>>>(proj_w, pwT_hi, pwT_lo, DD, DD); // 5
    conv_transpose_kernel<<<dim3(D4 / 32, DD / 32, LL), tb>>>(fc_w, fwT_hi, fwT_lo, DD, D4);   // 6
    conv_transpose_kernel<<<dim3(DD / 32, D4 / 32, LL), tb>>>(out_w, owT_hi, owT_lo, D4, DD);  // 7
    conv_wte_kernel<<<(VV * DD / 4 + 255) / 256, 256>>>(wte, wte_h, VV * DD / 4);              // 8

    for (int l = 0; l < LL; l++) {
        if (l > 0) {
            layernorm_h_kernel<<<MM, 256>>>(x, ln1_g + l * DD, ln1_b + l * DD, h_h);
            gemm_h<2,0,0,0><<<gQKV, 256, SM2>>>(
                h_h, awT_hi + (size_t)l * D3 * DD, awT_lo + (size_t)l * D3 * DD,
                attn_b + (size_t)l * D3, nullptr, qkv, nullptr, D3, DD);
            flash_attn_kernel<<<gATT, 256, ATT_SMEM>>>(qkv, at_h);
        }

        gemm_h<2,0,0,1><<<gPROJ, 256, SM2>>>(
            at_h, pwT_hi + (size_t)l * DD * DD, pwT_lo + (size_t)l * DD * DD,
            proj_b + (size_t)l * DD, x, x, nullptr, DD, DD);

        layernorm_h_kernel<<<MM, 256>>>(x, ln2_g + l * DD, ln2_b + l * DD, h_h);

        gemm_h<2,1,1,0><<<gFC, 256, SM2>>>(
            h_h, fwT_hi + (size_t)l * D4 * DD, fwT_lo + (size_t)l * D4 * DD,
            fc_b + (size_t)l * D4, nullptr, nullptr, fc_h, D4, DD);

        gemm_h<2,0,0,1><<<gOUT, 256, SM2>>>(
            fc_h, owT_hi + (size_t)l * DD * D4, owT_lo + (size_t)l * DD * D4,
            out_b + (size_t)l * DD, x, x, nullptr, DD, D4);
    }

    layernorm_h_kernel<<<MM, 256>>>(x, lnf_g, lnf_b, h_h);

    gemm_h<1,0,0,0><<<gLM, 256, SM1>>>(
        h_h, wte_h, nullptr, nullptr, nullptr, logits, nullptr, VV, DD);
}

// round 10
// speedup vs baseline: 7.3136x; 1.8971x over previous
#include <cuda_runtime.h>
#include <cuda_fp16.h>
#include <math.h>

// ---------------- problem constants ----------------
#define BB   2
#define TT   1024
#define DD   768
#define HH   12
#define HDIM 64
#define LL   4
#define VV   50257
#define MM   (BB*TT)      // 2048
#define D3   (3*DD)       // 2304
#define D4   (4*DD)       // 3072

// ---------------- GEMM config ----------------
#define BM 128
#define BN 128
#define BK 32
#define STAGES 3
#define ASTRIDE 40
#define MAT_BYTES (128 * ASTRIDE * 2)

// ---------------- attention config ----------------
#define HS  72                 // half stride for Q/K/V/P tiles (64 + 8 pad)
#define SSF 68                 // float stride for score tile
// layout: sQ | sK | sV (halves) | sS (floats) | sP (halves) | sScale | sInvL
#define SQ_OFF   0
#define SK_OFF   (64 * HS * 2)
#define SV_OFF   (2 * 64 * HS * 2)
#define SS_OFF   (3 * 64 * HS * 2)                  // 27648
#define SP_OFF   (SS_OFF + 64 * SSF * 4)            // 45056
#define SSC_OFF  (SP_OFF + 64 * HS * 2)             // 54272
#define SIL_OFF  (SSC_OFF + 256)                    // 54528
#define ATT_SMEM (SIL_OFF + 256)                    // 54784

// ---------------- scratch ----------------
__device__ float g_x [MM * DD];

__device__ __align__(16) __half g_qkv_h [MM * D3];
__device__ __align__(16) __half g_h_h   [MM * DD];
__device__ __align__(16) __half g_attn_h[MM * DD];
__device__ __align__(16) __half g_fc_h  [MM * D4];

__device__ __align__(16) __half g_attnwT_hi[LL * D3 * DD];
__device__ __align__(16) __half g_attnwT_lo[LL * D3 * DD];
__device__ __align__(16) __half g_projwT_hi[LL * DD * DD];
__device__ __align__(16) __half g_projwT_lo[LL * DD * DD];
__device__ __align__(16) __half g_fcwT_hi  [LL * D4 * DD];
__device__ __align__(16) __half g_fcwT_lo  [LL * D4 * DD];
__device__ __align__(16) __half g_outwT_hi [LL * DD * D4];
__device__ __align__(16) __half g_outwT_lo [LL * DD * D4];
__device__ __align__(16) __half g_wte_h    [VV * DD];

// ---------------- helpers ----------------
__device__ __forceinline__ void split2h(float x, __half& hi, __half& lo) {
    hi = __float2half_rn(x);
    lo = __float2half_rn(x - __half2float(hi));
}

__device__ __forceinline__ void mma_f16(float* c, const unsigned* a, const unsigned* b) {
    asm volatile(
        "mma.sync.aligned.m16n8k16.row.col.f32.f16.f16.f32 "
        "{%0,%1,%2,%3}, {%4,%5,%6,%7}, {%8,%9}, {%0,%1,%2,%3};"
        : "+f"(c[0]), "+f"(c[1]), "+f"(c[2]), "+f"(c[3])
        : "r"(a[0]), "r"(a[1]), "r"(a[2]), "r"(a[3]), "r"(b[0]), "r"(b[1]));
}

#define LDSM_X4(r0, r1, r2, r3, addr) \
    asm volatile("ldmatrix.sync.aligned.m8n8.x4.shared.b16 {%0,%1,%2,%3}, [%4];" \
                 : "=r"(r0), "=r"(r1), "=r"(r2), "=r"(r3) : "r"(addr))

#define LDSM_X4_T(r0, r1, r2, r3, addr) \
    asm volatile("ldmatrix.sync.aligned.m8n8.x4.trans.shared.b16 {%0,%1,%2,%3}, [%4];" \
                 : "=r"(r0), "=r"(r1), "=r"(r2), "=r"(r3) : "r"(addr))

#define CP_ASYNC16(saddr, gaddr, sz) \
    asm volatile("cp.async.cg.shared.global [%0], [%1], 16, %2;" \
                 :: "r"(saddr), "l"(gaddr), "r"(sz) : "memory")
#define CP_COMMIT() asm volatile("cp.async.commit_group;" ::: "memory")
#define CP_WAIT1()  asm volatile("cp.async.wait_group 1;" ::: "memory")

// ---------------- conversion kernels ----------------
__global__ void conv_wte_kernel(const float* __restrict__ src,
                                __half* __restrict__ dst, int n4) {
    int i = blockIdx.x * blockDim.x + threadIdx.x;
    if (i >= n4) return;
    float4 v = reinterpret_cast<const float4*>(src)[i];
    reinterpret_cast<__half2*>(dst)[2 * i]     = __half2(__float2half_rn(v.x), __float2half_rn(v.y));
    reinterpret_cast<__half2*>(dst)[2 * i + 1] = __half2(__float2half_rn(v.z), __float2half_rn(v.w));
}

__global__ void conv_transpose_kernel(const float* __restrict__ src,
                                      __half* __restrict__ dhi,
                                      __half* __restrict__ dlo,
                                      int Kd, int Nd) {
    int l = blockIdx.z;
    src += (size_t)l * Kd * Nd;
    dhi += (size_t)l * Nd * Kd;
    dlo += (size_t)l * Nd * Kd;
    __shared__ float t[32][33];
    int n0 = blockIdx.x * 32, k0 = blockIdx.y * 32;
    int tx = threadIdx.x, ty = threadIdx.y;
#pragma unroll
    for (int i = 0; i < 4; i++) {
        int k = k0 + ty + i * 8, n = n0 + tx;
        if (k < Kd && n < Nd) t[ty + i * 8][tx] = src[(size_t)k * Nd + n];
    }
    __syncthreads();
#pragma unroll
    for (int i = 0; i < 4; i++) {
        int n = n0 + ty + i * 8, k = k0 + tx;
        if (n < Nd && k < Kd) {
            __half h, lo;
            split2h(t[tx][ty + i * 8], h, lo);
            dhi[(size_t)n * Kd + k] = h;
            dlo[(size_t)n * Kd + k] = lo;
        }
    }
}

// ---------------- fused embed + layernorm(ln1 of layer 0) ----------------
__global__ void embed_ln_kernel(const int* __restrict__ ids,
                                const float* __restrict__ wte,
                                const float* __restrict__ wpe,
                                const float* __restrict__ g,
                                const float* __restrict__ b,
                                float* __restrict__ x,
                                __half* __restrict__ out) {
    int row = blockIdx.x;
    int tid = threadIdx.x;
    int t = row % TT;
    __shared__ float e[DD];
    __shared__ float red[256];
    __shared__ float s_mu, s_rstd;
    const float* wt = wte + (size_t)ids[row] * DD;
    const float* wp = wpe + (size_t)t * DD;

    float s = 0.f;
    for (int d = tid; d < DD; d += 256) {
        float v = wt[d] + wp[d];
        e[d] = v;
        x[(size_t)row * DD + d] = v;
        s += v;
    }
    red[tid] = s; __syncthreads();
    for (int o = 128; o > 0; o >>= 1) {
        if (tid < o) red[tid] += red[tid + o];
        __syncthreads();
    }
    if (tid == 0) s_mu = red[0] / DD;
    __syncthreads();
    float mu = s_mu;

    float v = 0.f;
    for (int d = tid; d < DD; d += 256) { float t2 = e[d] - mu; v += t2 * t2; }
    red[tid] = v; __syncthreads();
    for (int o = 128; o > 0; o >>= 1) {
        if (tid < o) red[tid] += red[tid + o];
        __syncthreads();
    }
    if (tid == 0) s_rstd = rsqrtf(red[0] / DD + 1e-5f);
    __syncthreads();
    float rstd = s_rstd;

    for (int d = tid; d < DD; d += 256)
        out[(size_t)row * DD + d] = __float2half_rn(g[d] * (e[d] - mu) * rstd + b[d]);
}

// ---------------- layernorm: fp32 in -> fp16 out -------------
__global__ void layernorm_h_kernel(const float* __restrict__ x,
                                   const float* __restrict__ g,
                                   const float* __restrict__ b,
                                   __half* __restrict__ out) {
    int row = blockIdx.x;
    int tid = threadIdx.x;
    __shared__ float red[256];
    __shared__ float s_mu, s_rstd;
    const float* xr = x + (size_t)row * DD;

    float s = 0.f;
    for (int d = tid; d < DD; d += 256) s += xr[d];
    red[tid] = s; __syncthreads();
    for (int o = 128; o > 0; o >>= 1) {
        if (tid < o) red[tid] += red[tid + o];
        __syncthreads();
    }
    if (tid == 0) s_mu = red[0] / DD;
    __syncthreads();
    float mu = s_mu;

    float v = 0.f;
    for (int d = tid; d < DD; d += 256) { float t = xr[d] - mu; v += t * t; }
    red[tid] = v; __syncthreads();
    for (int o = 128; o > 0; o >>= 1) {
        if (tid < o) red[tid] += red[tid + o];
        __syncthreads();
    }
    if (tid == 0) s_rstd = rsqrtf(red[0] / DD + 1e-5f);
    __syncthreads();
    float rstd = s_rstd;

    for (int d = tid; d < DD; d += 256)
        out[(size_t)row * DD + d] = __float2half_rn(g[d] * (xr[d] - mu) * rstd + b[d]);
}

// ---------------- flash attention (fp16 mma, online softmax) ----------------
// grid (TT/64, HH, BB), 256 threads / 8 warps.
// Warp w: group g=w>>1 handles query rows [g*16,g*16+16); half hw=w&1 handles
// keys [hw*32,hw*32+32). Scores via mma (Q,K fp16), fp32 to smem; softmax by all
// 256 threads (4/row, shuffles, __expf); P fp16 to smem; PV via mma with
// ldmatrix.trans on V. Per-warp O accum fp32, warp-pair combined via smem.
__global__ void __launch_bounds__(256, 2)
flash_attn_kernel(const __half* __restrict__ qkv, __half* __restrict__ oh) {
    extern __shared__ char smc[];
    __half* sQ = (__half*)(smc + SQ_OFF);
    __half* sK = (__half*)(smc + SK_OFF);
    __half* sV = (__half*)(smc + SV_OFF);
    float*  sS = (float*)(smc + SS_OFF);
    __half* sP = (__half*)(smc + SP_OFF);
    float*  sScale = (float*)(smc + SSC_OFF);
    float*  sInvL  = (float*)(smc + SIL_OFF);

    const int qt = gridDim.x - 1 - blockIdx.x;   // heavy tiles first
    const int h  = blockIdx.y;
    const int b  = blockIdx.z;
    const int tid  = threadIdx.x;
    const int lane = tid & 31;
    const int wid  = tid >> 5;
    const int g    = wid >> 1;
    const int hw   = wid & 1;
    const int lrow  = lane & 15;
    const int lcol8 = (lane >> 4) * 8;
    const int gp = lane >> 2;
    const int tg = lane & 3;

    const unsigned sQa = (unsigned)__cvta_generic_to_shared(sQ);
    const unsigned sKa = (unsigned)__cvta_generic_to_shared(sK);
    const unsigned sVa = (unsigned)__cvta_generic_to_shared(sV);
    const unsigned sPa = (unsigned)__cvta_generic_to_shared(sP);

    const size_t base = (size_t)b * TT * D3 + h * HDIM;

    // load Q tile (64 rows x 64 halves)
#pragma unroll
    for (int i = 0; i < 2; i++) {
        int idx = tid + 256 * i;
        int r = idx >> 3, c8 = (idx & 7) * 8;
        *(uint4*)(sQ + r * HS + c8) =
            *(const uint4*)(qkv + base + (size_t)(qt * 64 + r) * D3 + c8);
    }

    // softmax state: thread handles row sr, cols [sq4, sq4+16)
    const int sr = tid >> 2;
    const int sq4 = (tid & 3) * 16;
    float m = -1e30f, l = 0.f;

    float oa[8][4];
#pragma unroll
    for (int i = 0; i < 8; i++)
#pragma unroll
        for (int j = 0; j < 4; j++) oa[i][j] = 0.f;

    for (int kt = 0; kt <= qt; kt++) {
        __syncthreads();
#pragma unroll
        for (int i = 0; i < 2; i++) {
            int idx = tid + 256 * i;
            int r = idx >> 3, c8 = (idx & 7) * 8;
            size_t grow = base + (size_t)(kt * 64 + r) * D3;
            *(uint4*)(sK + r * HS + c8) = *(const uint4*)(qkv + grow + DD + c8);
            *(uint4*)(sV + r * HS + c8) = *(const uint4*)(qkv + grow + 2 * DD + c8);
        }
        __syncthreads();

        // ---- scores: warp computes 16q x 32k via mma ----
        {
            float sacc[4][4];
#pragma unroll
            for (int i = 0; i < 4; i++)
#pragma unroll
                for (int j = 0; j < 4; j++) sacc[i][j] = 0.f;
#pragma unroll
            for (int ks = 0; ks < 4; ks++) {
                unsigned av[4];
                LDSM_X4(av[0], av[1], av[2], av[3],
                        sQa + ((g * 16 + lrow) * HS + ks * 16 + lcol8) * 2);
                unsigned bf[4][2];
#pragma unroll
                for (int p = 0; p < 2; p++) {
                    unsigned t0, t1, t2, t3;
                    LDSM_X4(t0, t1, t2, t3,
                            sKa + ((hw * 32 + p * 16 + lrow) * HS + ks * 16 + lcol8) * 2);
                    bf[2 * p][0] = t0; bf[2 * p + 1][0] = t1;
                    bf[2 * p][1] = t2; bf[2 * p + 1][1] = t3;
                }
#pragma unroll
                for (int ni = 0; ni < 4; ni++) mma_f16(sacc[ni], av, bf[ni]);
            }
            const bool diag = (kt == qt);
            const int r0 = g * 16 + gp;
#pragma unroll
            for (int ni = 0; ni < 4; ni++) {
                int col = hw * 32 + ni * 8 + tg * 2;
                float c0 = sacc[ni][0] * 0.125f, c1 = sacc[ni][1] * 0.125f;
                float c2 = sacc[ni][2] * 0.125f, c3 = sacc[ni][3] * 0.125f;
                if (diag) {
                    if (col     > r0)     c0 = -1e30f;
                    if (col + 1 > r0)     c1 = -1e30f;
                    if (col     > r0 + 8) c2 = -1e30f;
                    if (col + 1 > r0 + 8) c3 = -1e30f;
                }
                sS[r0 * SSF + col] = c0;       sS[r0 * SSF + col + 1] = c1;
                sS[(r0 + 8) * SSF + col] = c2; sS[(r0 + 8) * SSF + col + 1] = c3;
            }
        }
        __syncthreads();

        // ---- softmax: 4 threads per row ----
        {
            const float* srow = sS + sr * SSF + sq4;
            float4 v0 = *(const float4*)(srow + 0);
            float4 v1 = *(const float4*)(srow + 4);
            float4 v2 = *(const float4*)(srow + 8);
            float4 v3 = *(const float4*)(srow + 12);
            float mt = fmaxf(fmaxf(fmaxf(v0.x, v0.y), fmaxf(v0.z, v0.w)),
                             fmaxf(fmaxf(v1.x, v1.y), fmaxf(v1.z, v1.w)));
            mt = fmaxf(mt, fmaxf(fmaxf(fmaxf(v2.x, v2.y), fmaxf(v2.z, v2.w)),
                                 fmaxf(fmaxf(v3.x, v3.y), fmaxf(v3.z, v3.w))));
            mt = fmaxf(mt, __shfl_xor_sync(0xffffffffu, mt, 1));
            mt = fmaxf(mt, __shfl_xor_sync(0xffffffffu, mt, 2));
            float newm = fmaxf(m, mt);
            float sc = __expf(m - newm);
            float p[16];
            p[0] = __expf(v0.x - newm); p[1] = __expf(v0.y - newm);
            p[2] = __expf(v0.z - newm); p[3] = __expf(v0.w - newm);
            p[4] = __expf(v1.x - newm); p[5] = __expf(v1.y - newm);
            p[6] = __expf(v1.z - newm); p[7] = __expf(v1.w - newm);
            p[8]  = __expf(v2.x - newm); p[9]  = __expf(v2.y - newm);
            p[10] = __expf(v2.z - newm); p[11] = __expf(v2.w - newm);
            p[12] = __expf(v3.x - newm); p[13] = __expf(v3.y - newm);
            p[14] = __expf(v3.z - newm); p[15] = __expf(v3.w - newm);
            float ls = 0.f;
#pragma unroll
            for (int i = 0; i < 16; i++) ls += p[i];
            ls += __shfl_xor_sync(0xffffffffu, ls, 1);
            ls += __shfl_xor_sync(0xffffffffu, ls, 2);
            l = l * sc + ls;
            m = newm;
            __half* prow = sP + sr * HS + sq4;
#pragma unroll
            for (int i = 0; i < 8; i++)
                *(__half2*)(prow + 2 * i) =
                    __half2(__float2half_rn(p[2 * i]), __float2half_rn(p[2 * i + 1]));
            if ((tid & 3) == 0) sScale[sr] = sc;
        }
        __syncthreads();

        // ---- PV: warp computes 16q x 64d over its 32 keys ----
        {
            float s0 = sScale[g * 16 + gp], s1 = sScale[g * 16 + gp + 8];
#pragma unroll
            for (int nt = 0; nt < 8; nt++) {
                oa[nt][0] *= s0; oa[nt][1] *= s0;
                oa[nt][2] *= s1; oa[nt][3] *= s1;
            }
#pragma unroll
            for (int ks = 0; ks < 2; ks++) {
                int k0 = hw * 32 + ks * 16;
                unsigned av[4];
                LDSM_X4(av[0], av[1], av[2], av[3],
                        sPa + ((g * 16 + lrow) * HS + k0 + lcol8) * 2);
                int vrow = k0 + ((lane >> 4) << 3) + (lane & 7);
                int vcol8 = ((lane >> 3) & 1) * 8;
#pragma unroll
                for (int dt = 0; dt < 4; dt++) {
                    unsigned t0, t1, t2, t3;
                    LDSM_X4_T(t0, t1, t2, t3,
                              sVa + (vrow * HS + dt * 16 + vcol8) * 2);
                    unsigned bf0[2] = {t0, t2};
                    unsigned bf1[2] = {t1, t3};
                    mma_f16(oa[2 * dt],     av, bf0);
                    mma_f16(oa[2 * dt + 1], av, bf1);
                }
            }
        }
    }

    __syncthreads();
    if ((tid & 3) == 0) sInvL[sr] = 1.0f / l;
    if (hw == 1) {
        const int r0 = g * 16 + gp;
#pragma unroll
        for (int nt = 0; nt < 8; nt++) {
            int c = nt * 8 + tg * 2;
            sS[r0 * SSF + c] = oa[nt][0];       sS[r0 * SSF + c + 1] = oa[nt][1];
            sS[(r0 + 8) * SSF + c] = oa[nt][2]; sS[(r0 + 8) * SSF + c + 1] = oa[nt][3];
        }
    }
    __syncthreads();
    if (hw == 0) {
        const int r0 = g * 16 + gp;
        float i0 = sInvL[r0], i1 = sInvL[r0 + 8];
        __half* o0 = oh + (size_t)(b * TT + qt * 64 + r0) * DD + h * HDIM;
        __half* o1 = oh + (size_t)(b * TT + qt * 64 + r0 + 8) * DD + h * HDIM;
#pragma unroll
        for (int nt = 0; nt < 8; nt++) {
            int c = nt * 8 + tg * 2;
            float v0 = (oa[nt][0] + sS[r0 * SSF + c]) * i0;
            float v1 = (oa[nt][1] + sS[r0 * SSF + c + 1]) * i0;
            float v2 = (oa[nt][2] + sS[(r0 + 8) * SSF + c]) * i1;
            float v3 = (oa[nt][3] + sS[(r0 + 8) * SSF + c + 1]) * i1;
            *(__half2*)(o0 + c) = __half2(__float2half_rn(v0), __float2half_rn(v1));
            *(__half2*)(o1 + c) = __half2(__float2half_rn(v2), __float2half_rn(v3));
        }
    }
}

// ---------------- fp16 GEMM (mma.sync m16n8k16 + ldmatrix) ----------------
template <int TERMS, int ACT, int WRITE_HALF, int HAS_RES>
__global__ void __launch_bounds__(256, 2)
gemm_h(const __half* __restrict__ A,
       const __half* __restrict__ Bhi, const __half* __restrict__ Blo,
       const float* __restrict__ bias, const float* __restrict__ residual,
       float* __restrict__ C, __half* __restrict__ Ch,
       int N, int K) {
    constexpr int NMAT = TERMS + 1;
    constexpr int STAGE_BYTES = NMAT * MAT_BYTES;
    constexpr unsigned A_OFF   = 0;
    constexpr unsigned BHI_OFF = MAT_BYTES;
    constexpr unsigned BLO_OFF = 2 * MAT_BYTES;

    extern __shared__ char sm[];
    const unsigned smb = (unsigned)__cvta_generic_to_shared(sm);

    const int tid  = threadIdx.x;
    const int lane = tid & 31;
    const int wid  = tid >> 5;
    const int wm   = (wid & 1) * 64;
    const int wn   = (wid >> 1) * 32;
    const int gp   = lane >> 2;
    const int tg   = lane & 3;
    const int row0 = blockIdx.y * BM;
    const int col0 = blockIdx.x * BN;
    const int nk   = K / BK;

    const int lrow  = lane & 15;
    const int lcol8 = (lane >> 4) * 8;

    const int lr = tid >> 1;
    const int lc = (tid & 1) * 16;
    const size_t aoff = (size_t)(row0 + lr) * K + lc;
    const int nrow = col0 + lr;
    const unsigned bsz = (nrow < N) ? 16u : 0u;
    const size_t boff = (size_t)((nrow < N) ? nrow : 0) * K + lc;
    const unsigned s_row = (unsigned)((lr * ASTRIDE + lc) * 2);

    float acc[4][4][4];
#pragma unroll
    for (int a = 0; a < 4; a++)
#pragma unroll
        for (int b = 0; b < 4; b++)
#pragma unroll
            for (int c = 0; c < 4; c++) acc[a][b][c] = 0.f;

    auto load_stage = [&](int slot, int k0) {
        unsigned base = smb + slot * STAGE_BYTES;
        const char* ga  = (const char*)(A + aoff + k0);
        const char* gbh = (const char*)(Bhi + boff + k0);
        CP_ASYNC16(base + A_OFF + s_row,        ga,       16u);
        CP_ASYNC16(base + A_OFF + s_row + 16,   ga + 16,  16u);
        CP_ASYNC16(base + BHI_OFF + s_row,      gbh,      bsz);
        CP_ASYNC16(base + BHI_OFF + s_row + 16, gbh + 16, bsz);
        if (TERMS == 2) {
            const char* gbl = (const char*)(Blo + boff + k0);
            CP_ASYNC16(base + BLO_OFF + s_row,      gbl,      bsz);
            CP_ASYNC16(base + BLO_OFF + s_row + 16, gbl + 16, bsz);
        }
    };

#pragma unroll
    for (int p = 0; p < STAGES - 1; p++) {
        if (p < nk) load_stage(p, p * BK);
        CP_COMMIT();
    }

    for (int kt = 0; kt < nk; kt++) {
        int ldk = kt + STAGES - 1;
        if (ldk < nk) load_stage(ldk % STAGES, ldk * BK);
        CP_COMMIT();
        CP_WAIT1();
        __syncthreads();

        const unsigned st = smb + (kt % STAGES) * STAGE_BYTES;

#pragma unroll
        for (int ks = 0; ks < 2; ks++) {
            const int kb = ks * 16 + lcol8;
            unsigned ar[4][4], bh[4][2], bl[4][2];
#pragma unroll
            for (int mi = 0; mi < 4; mi++) {
                unsigned ad = st + A_OFF + ((wm + mi * 16 + lrow) * ASTRIDE + kb) * 2;
                LDSM_X4(ar[mi][0], ar[mi][1], ar[mi][2], ar[mi][3], ad);
            }
#pragma unroll
            for (int p = 0; p < 2; p++) {
                unsigned bd = st + BHI_OFF + ((wn + p * 16 + lrow) * ASTRIDE + kb) * 2;
                unsigned t0, t1, t2, t3;
                LDSM_X4(t0, t1, t2, t3, bd);
                bh[2 * p][0] = t0; bh[2 * p + 1][0] = t1;
                bh[2 * p][1] = t2; bh[2 * p + 1][1] = t3;
                if (TERMS == 2) {
                    unsigned bd2 = st + BLO_OFF + ((wn + p * 16 + lrow) * ASTRIDE + kb) * 2;
                    LDSM_X4(t0, t1, t2, t3, bd2);
                    bl[2 * p][0] = t0; bl[2 * p + 1][0] = t1;
                    bl[2 * p][1] = t2; bl[2 * p + 1][1] = t3;
                }
            }
#pragma unroll
            for (int mi = 0; mi < 4; mi++)
#pragma unroll
                for (int ni = 0; ni < 4; ni++) {
                    mma_f16(acc[mi][ni], ar[mi], bh[ni]);
                    if (TERMS == 2) mma_f16(acc[mi][ni], ar[mi], bl[ni]);
                }
        }
        __syncthreads();
    }

#pragma unroll
    for (int mi = 0; mi < 4; mi++) {
        int rb = row0 + wm + mi * 16 + gp;
#pragma unroll
        for (int ni = 0; ni < 4; ni++) {
            int c = col0 + wn + ni * 8 + tg * 2;
            if (c >= N) continue;
            bool c1ok = (c + 1 < N);
#pragma unroll
            for (int half = 0; half < 2; half++) {
                int r = rb + half * 8;
                float v0 = acc[mi][ni][half * 2 + 0];
                float v1 = acc[mi][ni][half * 2 + 1];
                if (bias) { v0 += bias[c]; if (c1ok) v1 += bias[c + 1]; }
                if (ACT) {
                    v0 = 0.5f * v0 * (1.0f + erff(v0 * 0.70710678118654752f));
                    v1 = 0.5f * v1 * (1.0f + erff(v1 * 0.70710678118654752f));
                }
                if (WRITE_HALF) {
                    *reinterpret_cast<__half2*>(&Ch[(size_t)r * N + c]) =
                        __half2(__float2half_rn(v0), __float2half_rn(v1));
                } else {
                    if (HAS_RES) {
                        v0 += residual[(size_t)r * N + c];
                        if (c1ok) v1 += residual[(size_t)r * N + c + 1];
                    }
                    C[(size_t)r * N + c] = v0;
                    if (c1ok) C[(size_t)r * N + c + 1] = v1;
                }
            }
        }
    }
}

// ---------------- launch ----------------
extern "C" void kernel_launch(void* const* d_in, const int* in_sizes, int n_in,
                              void* d_out, int out_size) {
    const int*   ids    = (const int*)  d_in[0];
    const float* wte    = (const float*)d_in[1];
    const float* wpe    = (const float*)d_in[2];
    const float* ln1_g  = (const float*)d_in[3];
    const float* ln1_b  = (const float*)d_in[4];
    const float* attn_w = (const float*)d_in[5];
    const float* attn_b = (const float*)d_in[6];
    const float* proj_w = (const float*)d_in[7];
    const float* proj_b = (const float*)d_in[8];
    const float* ln2_g  = (const float*)d_in[9];
    const float* ln2_b  = (const float*)d_in[10];
    const float* fc_w   = (const float*)d_in[11];
    const float* fc_b   = (const float*)d_in[12];
    const float* out_w  = (const float*)d_in[13];
    const float* out_b  = (const float*)d_in[14];
    const float* lnf_g  = (const float*)d_in[15];
    const float* lnf_b  = (const float*)d_in[16];
    float* logits = (float*)d_out;

    float *x;
    __half *qkv_h, *h_h, *at_h, *fc_h;
    __half *awT_hi, *awT_lo, *pwT_hi, *pwT_lo, *fwT_hi, *fwT_lo, *owT_hi, *owT_lo, *wte_h;
    cudaGetSymbolAddress((void**)&x,      g_x);
    cudaGetSymbolAddress((void**)&qkv_h,  g_qkv_h);
    cudaGetSymbolAddress((void**)&h_h,    g_h_h);
    cudaGetSymbolAddress((void**)&at_h,   g_attn_h);
    cudaGetSymbolAddress((void**)&fc_h,   g_fc_h);
    cudaGetSymbolAddress((void**)&awT_hi, g_attnwT_hi);
    cudaGetSymbolAddress((void**)&awT_lo, g_attnwT_lo);
    cudaGetSymbolAddress((void**)&pwT_hi, g_projwT_hi);
    cudaGetSymbolAddress((void**)&pwT_lo, g_projwT_lo);
    cudaGetSymbolAddress((void**)&fwT_hi, g_fcwT_hi);
    cudaGetSymbolAddress((void**)&fwT_lo, g_fcwT_lo);
    cudaGetSymbolAddress((void**)&owT_hi, g_outwT_hi);
    cudaGetSymbolAddress((void**)&owT_lo, g_outwT_lo);
    cudaGetSymbolAddress((void**)&wte_h,  g_wte_h);

    const int SM2 = STAGES * 3 * MAT_BYTES;
    const int SM1 = STAGES * 2 * MAT_BYTES;
    cudaFuncSetAttribute(gemm_h<2,0,1,0>, cudaFuncAttributeMaxDynamicSharedMemorySize, SM2);
    cudaFuncSetAttribute(gemm_h<2,0,0,1>, cudaFuncAttributeMaxDynamicSharedMemorySize, SM2);
    cudaFuncSetAttribute(gemm_h<2,1,1,0>, cudaFuncAttributeMaxDynamicSharedMemorySize, SM2);
    cudaFuncSetAttribute(gemm_h<1,0,0,0>, cudaFuncAttributeMaxDynamicSharedMemorySize, SM1);
    cudaFuncSetAttribute(flash_attn_kernel, cudaFuncAttributeMaxDynamicSharedMemorySize, ATT_SMEM);

    dim3 tb(32, 8);
    const dim3 gQKV(D3 / BN, MM / BM), gPROJ(DD / BN, MM / BM),
               gFC(D4 / BN, MM / BM),  gOUT(DD / BN, MM / BM),
               gLM((VV + BN - 1) / BN, MM / BM),
               gATT(TT / 64, HH, BB);

    // order: ncu (-s 5 -c 1) captures the 4th launch -> flash_attn
    conv_transpose_kernel<<<dim3(D3 / 32, DD / 32, LL), tb>>>(attn_w, awT_hi, awT_lo, DD, D3); // 1
    embed_ln_kernel<<<MM, 256>>>(ids, wte, wpe, ln1_g, ln1_b, x, h_h);                         // 2
    gemm_h<2,0,1,0><<<gQKV, 256, SM2>>>(                                                       // 3
        h_h, awT_hi, awT_lo, attn_b, nullptr, nullptr, qkv_h, D3, DD);
    flash_attn_kernel<<<gATT, 256, ATT_SMEM>>>(qkv_h, at_h);                                   // 4 <- profiled
    conv_transpose_kernel<<<dim3(DD / 32, DD / 32, LL), tb>>>(proj_w, pwT_hi, pwT_lo, DD, DD); // 5
    conv_transpose_kernel<<<dim3(D4 / 32, DD / 32, LL), tb>>>(fc_w, fwT_hi, fwT_lo, DD, D4);   // 6
    conv_transpose_kernel<<<dim3(DD / 32, D4 / 32, LL), tb>>>(out_w, owT_hi, owT_lo, D4, DD);  // 7
    conv_wte_kernel<<<(VV * DD / 4 + 255) / 256, 256>>>(wte, wte_h, VV * DD / 4);              // 8

    for (int l = 0; l < LL; l++) {
        if (l > 0) {
            layernorm_h_kernel<<<MM, 256>>>(x, ln1_g + l * DD, ln1_b + l * DD, h_h);
            gemm_h<2,0,1,0><<<gQKV, 256, SM2>>>(
                h_h, awT_hi + (size_t)l * D3 * DD, awT_lo + (size_t)l * D3 * DD,
                attn_b + (size_t)l * D3, nullptr, nullptr, qkv_h, D3, DD);
            flash_attn_kernel<<<gATT, 256, ATT_SMEM>>>(qkv_h, at_h);
        }

        gemm_h<2,0,0,1><<<gPROJ, 256, SM2>>>(
            at_h, pwT_hi + (size_t)l * DD * DD, pwT_lo + (size_t)l * DD * DD,
            proj_b + (size_t)l * DD, x, x, nullptr, DD, DD);

        layernorm_h_kernel<<<MM, 256>>>(x, ln2_g + l * DD, ln2_b + l * DD, h_h);

        gemm_h<2,1,1,0><<<gFC, 256, SM2>>>(
            h_h, fwT_hi + (size_t)l * D4 * DD, fwT_lo + (size_t)l * D4 * DD,
            fc_b + (size_t)l * D4, nullptr, nullptr, fc_h, D4, DD);

        gemm_h<2,0,0,1><<<gOUT, 256, SM2>>>(
            fc_h, owT_hi + (size_t)l * DD * D4, owT_lo + (size_t)l * DD * D4,
            out_b + (size_t)l * DD, x, x, nullptr, DD, D4);
    }

    layernorm_h_kernel<<<MM, 256>>>(x, lnf_g, lnf_b, h_h);

    gemm_h<1,0,0,0><<<gLM, 256, SM1>>>(
        h_h, wte_h, nullptr, nullptr, nullptr, logits, nullptr, VV, DD);
}

// round 11
// speedup vs baseline: 7.6114x; 1.0407x over previous
#include <cuda_runtime.h>
#include <cuda_fp16.h>
#include <math.h>

// ---------------- problem constants ----------------
#define BB   2
#define TT   1024
#define DD   768
#define HH   12
#define HDIM 64
#define LL   4
#define VV   50257
#define MM   (BB*TT)      // 2048
#define D3   (3*DD)       // 2304
#define D4   (4*DD)       // 3072

// ---------------- GEMM config ----------------
#define BM 128
#define BN 128
#define BK 32
#define STAGES 3
#define ASTRIDE 40
#define MAT_BYTES (128 * ASTRIDE * 2)

// ---------------- attention config ----------------
#define HS  72
#define SSF 68
#define SQ_OFF   0
#define SK_OFF   (64 * HS * 2)
#define SV_OFF   (2 * 64 * HS * 2)
#define SS_OFF   (3 * 64 * HS * 2)
#define SP_OFF   (SS_OFF + 64 * SSF * 4)
#define SSC_OFF  (SP_OFF + 64 * HS * 2)
#define SIL_OFF  (SSC_OFF + 256)
#define ATT_SMEM (SIL_OFF + 256)

// ---------------- scratch ----------------
__device__ float g_x [MM * DD];

__device__ __align__(16) __half g_qkv_h [MM * D3];
__device__ __align__(16) __half g_h_h   [MM * DD];
__device__ __align__(16) __half g_attn_h[MM * DD];
__device__ __align__(16) __half g_fc_h  [MM * D4];

__device__ __align__(16) __half g_attnwT_hi[LL * D3 * DD];
__device__ __align__(16) __half g_attnwT_lo[LL * D3 * DD];
__device__ __align__(16) __half g_projwT_hi[LL * DD * DD];
__device__ __align__(16) __half g_projwT_lo[LL * DD * DD];
__device__ __align__(16) __half g_fcwT_hi  [LL * D4 * DD];
__device__ __align__(16) __half g_fcwT_lo  [LL * D4 * DD];
__device__ __align__(16) __half g_outwT_hi [LL * DD * D4];
__device__ __align__(16) __half g_outwT_lo [LL * DD * D4];
__device__ __align__(16) __half g_wte_h    [VV * DD];

// ---------------- helpers ----------------
__device__ __forceinline__ void split2h(float x, __half& hi, __half& lo) {
    hi = __float2half_rn(x);
    lo = __float2half_rn(x - __half2float(hi));
}

__device__ __forceinline__ void mma_f16(float* c, const unsigned* a, const unsigned* b) {
    asm volatile(
        "mma.sync.aligned.m16n8k16.row.col.f32.f16.f16.f32 "
        "{%0,%1,%2,%3}, {%4,%5,%6,%7}, {%8,%9}, {%0,%1,%2,%3};"
        : "+f"(c[0]), "+f"(c[1]), "+f"(c[2]), "+f"(c[3])
        : "r"(a[0]), "r"(a[1]), "r"(a[2]), "r"(a[3]), "r"(b[0]), "r"(b[1]));
}

#define LDSM_X4(r0, r1, r2, r3, addr) \
    asm volatile("ldmatrix.sync.aligned.m8n8.x4.shared.b16 {%0,%1,%2,%3}, [%4];" \
                 : "=r"(r0), "=r"(r1), "=r"(r2), "=r"(r3) : "r"(addr))

#define LDSM_X4_T(r0, r1, r2, r3, addr) \
    asm volatile("ldmatrix.sync.aligned.m8n8.x4.trans.shared.b16 {%0,%1,%2,%3}, [%4];" \
                 : "=r"(r0), "=r"(r1), "=r"(r2), "=r"(r3) : "r"(addr))

#define CP_ASYNC16(saddr, gaddr, sz) \
    asm volatile("cp.async.cg.shared.global [%0], [%1], 16, %2;" \
                 :: "r"(saddr), "l"(gaddr), "r"(sz) : "memory")
#define CP_COMMIT() asm volatile("cp.async.commit_group;" ::: "memory")
#define CP_WAIT_1() asm volatile("cp.async.wait_group 1;" ::: "memory")

// ---------------- conversion kernels ----------------
// 8 fp32 -> 8 fp16 per thread (one uint4 store)
__global__ void conv_wte_kernel(const float* __restrict__ src,
                                __half* __restrict__ dst, int n8) {
    int i = blockIdx.x * blockDim.x + threadIdx.x;
    if (i >= n8) return;
    float4 a = reinterpret_cast<const float4*>(src)[2 * i];
    float4 b = reinterpret_cast<const float4*>(src)[2 * i + 1];
    __half2 p0 = __floats2half2_rn(a.x, a.y);
    __half2 p1 = __floats2half2_rn(a.z, a.w);
    __half2 p2 = __floats2half2_rn(b.x, b.y);
    __half2 p3 = __floats2half2_rn(b.z, b.w);
    uint4 o;
    o.x = *reinterpret_cast<unsigned*>(&p0);
    o.y = *reinterpret_cast<unsigned*>(&p1);
    o.z = *reinterpret_cast<unsigned*>(&p2);
    o.w = *reinterpret_cast<unsigned*>(&p3);
    reinterpret_cast<uint4*>(dst)[i] = o;
}

__global__ void conv_transpose_kernel(const float* __restrict__ src,
                                      __half* __restrict__ dhi,
                                      __half* __restrict__ dlo,
                                      int Kd, int Nd) {
    int l = blockIdx.z;
    src += (size_t)l * Kd * Nd;
    dhi += (size_t)l * Nd * Kd;
    dlo += (size_t)l * Nd * Kd;
    __shared__ float t[32][33];
    int n0 = blockIdx.x * 32, k0 = blockIdx.y * 32;
    int tx = threadIdx.x, ty = threadIdx.y;
#pragma unroll
    for (int i = 0; i < 4; i++) {
        int k = k0 + ty + i * 8, n = n0 + tx;
        if (k < Kd && n < Nd) t[ty + i * 8][tx] = src[(size_t)k * Nd + n];
    }
    __syncthreads();
#pragma unroll
    for (int i = 0; i < 4; i++) {
        int n = n0 + ty + i * 8, k = k0 + tx;
        if (n < Nd && k < Kd) {
            __half h, lo;
            split2h(t[tx][ty + i * 8], h, lo);
            dhi[(size_t)n * Kd + k] = h;
            dlo[(size_t)n * Kd + k] = lo;
        }
    }
}

// ---------------- fused embed + layernorm(ln1 of layer 0) ----------------
__global__ void embed_ln_kernel(const int* __restrict__ ids,
                                const float* __restrict__ wte,
                                const float* __restrict__ wpe,
                                const float* __restrict__ g,
                                const float* __restrict__ b,
                                float* __restrict__ x,
                                __half* __restrict__ out) {
    int row = blockIdx.x;
    int tid = threadIdx.x;
    int t = row % TT;
    __shared__ float e[DD];
    __shared__ float red[256];
    __shared__ float s_mu, s_rstd;
    const float* wt = wte + (size_t)ids[row] * DD;
    const float* wp = wpe + (size_t)t * DD;

    float s = 0.f;
    for (int d = tid; d < DD; d += 256) {
        float v = wt[d] + wp[d];
        e[d] = v;
        x[(size_t)row * DD + d] = v;
        s += v;
    }
    red[tid] = s; __syncthreads();
    for (int o = 128; o > 0; o >>= 1) {
        if (tid < o) red[tid] += red[tid + o];
        __syncthreads();
    }
    if (tid == 0) s_mu = red[0] / DD;
    __syncthreads();
    float mu = s_mu;

    float v = 0.f;
    for (int d = tid; d < DD; d += 256) { float t2 = e[d] - mu; v += t2 * t2; }
    red[tid] = v; __syncthreads();
    for (int o = 128; o > 0; o >>= 1) {
        if (tid < o) red[tid] += red[tid + o];
        __syncthreads();
    }
    if (tid == 0) s_rstd = rsqrtf(red[0] / DD + 1e-5f);
    __syncthreads();
    float rstd = s_rstd;

    for (int d = tid; d < DD; d += 256)
        out[(size_t)row * DD + d] = __float2half_rn(g[d] * (e[d] - mu) * rstd + b[d]);
}

// ---------------- layernorm: fp32 in -> fp16 out -------------
__global__ void layernorm_h_kernel(const float* __restrict__ x,
                                   const float* __restrict__ g,
                                   const float* __restrict__ b,
                                   __half* __restrict__ out) {
    int row = blockIdx.x;
    int tid = threadIdx.x;
    __shared__ float red[256];
    __shared__ float s_mu, s_rstd;
    const float* xr = x + (size_t)row * DD;

    float s = 0.f;
    for (int d = tid; d < DD; d += 256) s += xr[d];
    red[tid] = s; __syncthreads();
    for (int o = 128; o > 0; o >>= 1) {
        if (tid < o) red[tid] += red[tid + o];
        __syncthreads();
    }
    if (tid == 0) s_mu = red[0] / DD;
    __syncthreads();
    float mu = s_mu;

    float v = 0.f;
    for (int d = tid; d < DD; d += 256) { float t = xr[d] - mu; v += t * t; }
    red[tid] = v; __syncthreads();
    for (int o = 128; o > 0; o >>= 1) {
        if (tid < o) red[tid] += red[tid + o];
        __syncthreads();
    }
    if (tid == 0) s_rstd = rsqrtf(red[0] / DD + 1e-5f);
    __syncthreads();
    float rstd = s_rstd;

    for (int d = tid; d < DD; d += 256)
        out[(size_t)row * DD + d] = __float2half_rn(g[d] * (xr[d] - mu) * rstd + b[d]);
}

// ---------------- flash attention (fp16 mma, online softmax) ----------------
__global__ void __launch_bounds__(256, 2)
flash_attn_kernel(const __half* __restrict__ qkv, __half* __restrict__ oh) {
    extern __shared__ char smc[];
    __half* sQ = (__half*)(smc + SQ_OFF);
    __half* sK = (__half*)(smc + SK_OFF);
    __half* sV = (__half*)(smc + SV_OFF);
    float*  sS = (float*)(smc + SS_OFF);
    __half* sP = (__half*)(smc + SP_OFF);
    float*  sScale = (float*)(smc + SSC_OFF);
    float*  sInvL  = (float*)(smc + SIL_OFF);

    const int qt = gridDim.x - 1 - blockIdx.x;
    const int h  = blockIdx.y;
    const int b  = blockIdx.z;
    const int tid  = threadIdx.x;
    const int lane = tid & 31;
    const int wid  = tid >> 5;
    const int g    = wid >> 1;
    const int hw   = wid & 1;
    const int lrow  = lane & 15;
    const int lcol8 = (lane >> 4) * 8;
    const int gp = lane >> 2;
    const int tg = lane & 3;

    const unsigned sQa = (unsigned)__cvta_generic_to_shared(sQ);
    const unsigned sKa = (unsigned)__cvta_generic_to_shared(sK);
    const unsigned sVa = (unsigned)__cvta_generic_to_shared(sV);
    const unsigned sPa = (unsigned)__cvta_generic_to_shared(sP);

    const size_t base = (size_t)b * TT * D3 + h * HDIM;

#pragma unroll
    for (int i = 0; i < 2; i++) {
        int idx = tid + 256 * i;
        int r = idx >> 3, c8 = (idx & 7) * 8;
        *(uint4*)(sQ + r * HS + c8) =
            *(const uint4*)(qkv + base + (size_t)(qt * 64 + r) * D3 + c8);
    }

    const int sr = tid >> 2;
    const int sq4 = (tid & 3) * 16;
    float m = -1e30f, l = 0.f;

    float oa[8][4];
#pragma unroll
    for (int i = 0; i < 8; i++)
#pragma unroll
        for (int j = 0; j < 4; j++) oa[i][j] = 0.f;

    for (int kt = 0; kt <= qt; kt++) {
        __syncthreads();
#pragma unroll
        for (int i = 0; i < 2; i++) {
            int idx = tid + 256 * i;
            int r = idx >> 3, c8 = (idx & 7) * 8;
            size_t grow = base + (size_t)(kt * 64 + r) * D3;
            *(uint4*)(sK + r * HS + c8) = *(const uint4*)(qkv + grow + DD + c8);
            *(uint4*)(sV + r * HS + c8) = *(const uint4*)(qkv + grow + 2 * DD + c8);
        }
        __syncthreads();

        // ---- scores ----
        {
            float sacc[4][4];
#pragma unroll
            for (int i = 0; i < 4; i++)
#pragma unroll
                for (int j = 0; j < 4; j++) sacc[i][j] = 0.f;
#pragma unroll
            for (int ks = 0; ks < 4; ks++) {
                unsigned av[4];
                LDSM_X4(av[0], av[1], av[2], av[3],
                        sQa + ((g * 16 + lrow) * HS + ks * 16 + lcol8) * 2);
                unsigned bf[4][2];
#pragma unroll
                for (int p = 0; p < 2; p++) {
                    unsigned t0, t1, t2, t3;
                    LDSM_X4(t0, t1, t2, t3,
                            sKa + ((hw * 32 + p * 16 + lrow) * HS + ks * 16 + lcol8) * 2);
                    bf[2 * p][0] = t0; bf[2 * p + 1][0] = t1;
                    bf[2 * p][1] = t2; bf[2 * p + 1][1] = t3;
                }
#pragma unroll
                for (int ni = 0; ni < 4; ni++) mma_f16(sacc[ni], av, bf[ni]);
            }
            const bool diag = (kt == qt);
            const int r0 = g * 16 + gp;
#pragma unroll
            for (int ni = 0; ni < 4; ni++) {
                int col = hw * 32 + ni * 8 + tg * 2;
                float c0 = sacc[ni][0] * 0.125f, c1 = sacc[ni][1] * 0.125f;
                float c2 = sacc[ni][2] * 0.125f, c3 = sacc[ni][3] * 0.125f;
                if (diag) {
                    if (col     > r0)     c0 = -1e30f;
                    if (col + 1 > r0)     c1 = -1e30f;
                    if (col     > r0 + 8) c2 = -1e30f;
                    if (col + 1 > r0 + 8) c3 = -1e30f;
                }
                sS[r0 * SSF + col] = c0;       sS[r0 * SSF + col + 1] = c1;
                sS[(r0 + 8) * SSF + col] = c2; sS[(r0 + 8) * SSF + col + 1] = c3;
            }
        }
        __syncthreads();

        // ---- softmax ----
        {
            const float* srow = sS + sr * SSF + sq4;
            float4 v0 = *(const float4*)(srow + 0);
            float4 v1 = *(const float4*)(srow + 4);
            float4 v2 = *(const float4*)(srow + 8);
            float4 v3 = *(const float4*)(srow + 12);
            float mt = fmaxf(fmaxf(fmaxf(v0.x, v0.y), fmaxf(v0.z, v0.w)),
                             fmaxf(fmaxf(v1.x, v1.y), fmaxf(v1.z, v1.w)));
            mt = fmaxf(mt, fmaxf(fmaxf(fmaxf(v2.x, v2.y), fmaxf(v2.z, v2.w)),
                                 fmaxf(fmaxf(v3.x, v3.y), fmaxf(v3.z, v3.w))));
            mt = fmaxf(mt, __shfl_xor_sync(0xffffffffu, mt, 1));
            mt = fmaxf(mt, __shfl_xor_sync(0xffffffffu, mt, 2));
            float newm = fmaxf(m, mt);
            float sc = __expf(m - newm);
            float p[16];
            p[0] = __expf(v0.x - newm); p[1] = __expf(v0.y - newm);
            p[2] = __expf(v0.z - newm); p[3] = __expf(v0.w - newm);
            p[4] = __expf(v1.x - newm); p[5] = __expf(v1.y - newm);
            p[6] = __expf(v1.z - newm); p[7] = __expf(v1.w - newm);
            p[8]  = __expf(v2.x - newm); p[9]  = __expf(v2.y - newm);
            p[10] = __expf(v2.z - newm); p[11] = __expf(v2.w - newm);
            p[12] = __expf(v3.x - newm); p[13] = __expf(v3.y - newm);
            p[14] = __expf(v3.z - newm); p[15] = __expf(v3.w - newm);
            float ls = 0.f;
#pragma unroll
            for (int i = 0; i < 16; i++) ls += p[i];
            ls += __shfl_xor_sync(0xffffffffu, ls, 1);
            ls += __shfl_xor_sync(0xffffffffu, ls, 2);
            l = l * sc + ls;
            m = newm;
            __half* prow = sP + sr * HS + sq4;
#pragma unroll
            for (int i = 0; i < 8; i++)
                *(__half2*)(prow + 2 * i) =
                    __half2(__float2half_rn(p[2 * i]), __float2half_rn(p[2 * i + 1]));
            if ((tid & 3) == 0) sScale[sr] = sc;
        }
        __syncthreads();

        // ---- PV ----
        {
            float s0 = sScale[g * 16 + gp], s1 = sScale[g * 16 + gp + 8];
#pragma unroll
            for (int nt = 0; nt < 8; nt++) {
                oa[nt][0] *= s0; oa[nt][1] *= s0;
                oa[nt][2] *= s1; oa[nt][3] *= s1;
            }
#pragma unroll
            for (int ks = 0; ks < 2; ks++) {
                int k0 = hw * 32 + ks * 16;
                unsigned av[4];
                LDSM_X4(av[0], av[1], av[2], av[3],
                        sPa + ((g * 16 + lrow) * HS + k0 + lcol8) * 2);
                int vrow = k0 + ((lane >> 4) << 3) + (lane & 7);
                int vcol8 = ((lane >> 3) & 1) * 8;
#pragma unroll
                for (int dt = 0; dt < 4; dt++) {
                    unsigned t0, t1, t2, t3;
                    LDSM_X4_T(t0, t1, t2, t3,
                              sVa + (vrow * HS + dt * 16 + vcol8) * 2);
                    unsigned bf0[2] = {t0, t2};
                    unsigned bf1[2] = {t1, t3};
                    mma_f16(oa[2 * dt],     av, bf0);
                    mma_f16(oa[2 * dt + 1], av, bf1);
                }
            }
        }
    }

    __syncthreads();
    if ((tid & 3) == 0) sInvL[sr] = 1.0f / l;
    if (hw == 1) {
        const int r0 = g * 16 + gp;
#pragma unroll
        for (int nt = 0; nt < 8; nt++) {
            int c = nt * 8 + tg * 2;
            sS[r0 * SSF + c] = oa[nt][0];       sS[r0 * SSF + c + 1] = oa[nt][1];
            sS[(r0 + 8) * SSF + c] = oa[nt][2]; sS[(r0 + 8) * SSF + c + 1] = oa[nt][3];
        }
    }
    __syncthreads();
    if (hw == 0) {
        const int r0 = g * 16 + gp;
        float i0 = sInvL[r0], i1 = sInvL[r0 + 8];
        __half* o0 = oh + (size_t)(b * TT + qt * 64 + r0) * DD + h * HDIM;
        __half* o1 = oh + (size_t)(b * TT + qt * 64 + r0 + 8) * DD + h * HDIM;
#pragma unroll
        for (int nt = 0; nt < 8; nt++) {
            int c = nt * 8 + tg * 2;
            float v0 = (oa[nt][0] + sS[r0 * SSF + c]) * i0;
            float v1 = (oa[nt][1] + sS[r0 * SSF + c + 1]) * i0;
            float v2 = (oa[nt][2] + sS[(r0 + 8) * SSF + c]) * i1;
            float v3 = (oa[nt][3] + sS[(r0 + 8) * SSF + c + 1]) * i1;
            *(__half2*)(o0 + c) = __half2(__float2half_rn(v0), __float2half_rn(v1));
            *(__half2*)(o1 + c) = __half2(__float2half_rn(v2), __float2half_rn(v3));
        }
    }
}

// ---------------- fp16 GEMM (single-sync multistage pipeline) ----------------
// TERMS==2: C = A.(Bhi+Blo)^T ; TERMS==1: C = A.B^T
template <int TERMS, int ACT, int WRITE_HALF, int HAS_RES>
__global__ void __launch_bounds__(256, 2)
gemm_h(const __half* __restrict__ A,
       const __half* __restrict__ Bhi, const __half* __restrict__ Blo,
       const float* __restrict__ bias, const float* __restrict__ residual,
       float* __restrict__ C, __half* __restrict__ Ch,
       int N, int K) {
    constexpr int NMAT = TERMS + 1;
    constexpr int STAGE_BYTES = NMAT * MAT_BYTES;
    constexpr unsigned A_OFF   = 0;
    constexpr unsigned BHI_OFF = MAT_BYTES;
    constexpr unsigned BLO_OFF = 2 * MAT_BYTES;

    extern __shared__ char sm[];
    const unsigned smb = (unsigned)__cvta_generic_to_shared(sm);

    const int tid  = threadIdx.x;
    const int lane = tid & 31;
    const int wid  = tid >> 5;
    const int wm   = (wid & 1) * 64;
    const int wn   = (wid >> 1) * 32;
    const int gp   = lane >> 2;
    const int tg   = lane & 3;
    const int row0 = blockIdx.y * BM;
    const int col0 = blockIdx.x * BN;
    const int nk   = K / BK;

    const int lrow  = lane & 15;
    const int lcol8 = (lane >> 4) * 8;

    const int lr = tid >> 1;
    const int lc = (tid & 1) * 16;
    const size_t aoff = (size_t)(row0 + lr) * K + lc;
    const int nrow = col0 + lr;
    const unsigned bsz = (nrow < N) ? 16u : 0u;
    const size_t boff = (size_t)((nrow < N) ? nrow : 0) * K + lc;
    const unsigned s_row = (unsigned)((lr * ASTRIDE + lc) * 2);

    float acc[4][4][4];
#pragma unroll
    for (int a = 0; a < 4; a++)
#pragma unroll
        for (int b = 0; b < 4; b++)
#pragma unroll
            for (int c = 0; c < 4; c++) acc[a][b][c] = 0.f;

    auto load_stage = [&](int slot, int k0) {
        unsigned base = smb + slot * STAGE_BYTES;
        const char* ga  = (const char*)(A + aoff + k0);
        const char* gbh = (const char*)(Bhi + boff + k0);
        CP_ASYNC16(base + A_OFF + s_row,        ga,       16u);
        CP_ASYNC16(base + A_OFF + s_row + 16,   ga + 16,  16u);
        CP_ASYNC16(base + BHI_OFF + s_row,      gbh,      bsz);
        CP_ASYNC16(base + BHI_OFF + s_row + 16, gbh + 16, bsz);
        if (TERMS == 2) {
            const char* gbl = (const char*)(Blo + boff + k0);
            CP_ASYNC16(base + BLO_OFF + s_row,      gbl,      bsz);
            CP_ASYNC16(base + BLO_OFF + s_row + 16, gbl + 16, bsz);
        }
    };

    // prologue: fill STAGES-1 stages
#pragma unroll
    for (int p = 0; p < STAGES - 1; p++) {
        if (p < nk) load_stage(p, p * BK);
        CP_COMMIT();
    }

    for (int kt = 0; kt < nk; kt++) {
        CP_WAIT_1();          // stage kt complete (2 newer groups may be in flight)
        __syncthreads();      // single barrier: also protects slot reuse (WAR)

        int ldk = kt + STAGES - 1;
        if (ldk < nk) load_stage(ldk % STAGES, ldk * BK);
        CP_COMMIT();

        const unsigned st = smb + (kt % STAGES) * STAGE_BYTES;

#pragma unroll
        for (int ks = 0; ks < 2; ks++) {
            const int kb = ks * 16 + lcol8;
            unsigned ar[4][4], bh[4][2], bl[4][2];
#pragma unroll
            for (int mi = 0; mi < 4; mi++) {
                unsigned ad = st + A_OFF + ((wm + mi * 16 + lrow) * ASTRIDE + kb) * 2;
                LDSM_X4(ar[mi][0], ar[mi][1], ar[mi][2], ar[mi][3], ad);
            }
#pragma unroll
            for (int p = 0; p < 2; p++) {
                unsigned bd = st + BHI_OFF + ((wn + p * 16 + lrow) * ASTRIDE + kb) * 2;
                unsigned t0, t1, t2, t3;
                LDSM_X4(t0, t1, t2, t3, bd);
                bh[2 * p][0] = t0; bh[2 * p + 1][0] = t1;
                bh[2 * p][1] = t2; bh[2 * p + 1][1] = t3;
                if (TERMS == 2) {
                    unsigned bd2 = st + BLO_OFF + ((wn + p * 16 + lrow) * ASTRIDE + kb) * 2;
                    LDSM_X4(t0, t1, t2, t3, bd2);
                    bl[2 * p][0] = t0; bl[2 * p + 1][0] = t1;
                    bl[2 * p][1] = t2; bl[2 * p + 1][1] = t3;
                }
            }
#pragma unroll
            for (int mi = 0; mi < 4; mi++)
#pragma unroll
                for (int ni = 0; ni < 4; ni++) {
                    mma_f16(acc[mi][ni], ar[mi], bh[ni]);
                    if (TERMS == 2) mma_f16(acc[mi][ni], ar[mi], bl[ni]);
                }
        }
    }

#pragma unroll
    for (int mi = 0; mi < 4; mi++) {
        int rb = row0 + wm + mi * 16 + gp;
#pragma unroll
        for (int ni = 0; ni < 4; ni++) {
            int c = col0 + wn + ni * 8 + tg * 2;
            if (c >= N) continue;
            bool c1ok = (c + 1 < N);
#pragma unroll
            for (int half = 0; half < 2; half++) {
                int r = rb + half * 8;
                float v0 = acc[mi][ni][half * 2 + 0];
                float v1 = acc[mi][ni][half * 2 + 1];
                if (bias) { v0 += bias[c]; if (c1ok) v1 += bias[c + 1]; }
                if (ACT) {
                    v0 = 0.5f * v0 * (1.0f + erff(v0 * 0.70710678118654752f));
                    v1 = 0.5f * v1 * (1.0f + erff(v1 * 0.70710678118654752f));
                }
                if (WRITE_HALF) {
                    *reinterpret_cast<__half2*>(&Ch[(size_t)r * N + c]) =
                        __half2(__float2half_rn(v0), __float2half_rn(v1));
                } else {
                    if (HAS_RES) {
                        v0 += residual[(size_t)r * N + c];
                        if (c1ok) v1 += residual[(size_t)r * N + c + 1];
                    }
                    C[(size_t)r * N + c] = v0;
                    if (c1ok) C[(size_t)r * N + c + 1] = v1;
                }
            }
        }
    }
}

// ---------------- launch ----------------
extern "C" void kernel_launch(void* const* d_in, const int* in_sizes, int n_in,
                              void* d_out, int out_size) {
    const int*   ids    = (const int*)  d_in[0];
    const float* wte    = (const float*)d_in[1];
    const float* wpe    = (const float*)d_in[2];
    const float* ln1_g  = (const float*)d_in[3];
    const float* ln1_b  = (const float*)d_in[4];
    const float* attn_w = (const float*)d_in[5];
    const float* attn_b = (const float*)d_in[6];
    const float* proj_w = (const float*)d_in[7];
    const float* proj_b = (const float*)d_in[8];
    const float* ln2_g  = (const float*)d_in[9];
    const float* ln2_b  = (const float*)d_in[10];
    const float* fc_w   = (const float*)d_in[11];
    const float* fc_b   = (const float*)d_in[12];
    const float* out_w  = (const float*)d_in[13];
    const float* out_b  = (const float*)d_in[14];
    const float* lnf_g  = (const float*)d_in[15];
    const float* lnf_b  = (const float*)d_in[16];
    float* logits = (float*)d_out;

    float *x;
    __half *qkv_h, *h_h, *at_h, *fc_h;
    __half *awT_hi, *awT_lo, *pwT_hi, *pwT_lo, *fwT_hi, *fwT_lo, *owT_hi, *owT_lo, *wte_h;
    cudaGetSymbolAddress((void**)&x,      g_x);
    cudaGetSymbolAddress((void**)&qkv_h,  g_qkv_h);
    cudaGetSymbolAddress((void**)&h_h,    g_h_h);
    cudaGetSymbolAddress((void**)&at_h,   g_attn_h);
    cudaGetSymbolAddress((void**)&fc_h,   g_fc_h);
    cudaGetSymbolAddress((void**)&awT_hi, g_attnwT_hi);
    cudaGetSymbolAddress((void**)&awT_lo, g_attnwT_lo);
    cudaGetSymbolAddress((void**)&pwT_hi, g_projwT_hi);
    cudaGetSymbolAddress((void**)&pwT_lo, g_projwT_lo);
    cudaGetSymbolAddress((void**)&fwT_hi, g_fcwT_hi);
    cudaGetSymbolAddress((void**)&fwT_lo, g_fcwT_lo);
    cudaGetSymbolAddress((void**)&owT_hi, g_outwT_hi);
    cudaGetSymbolAddress((void**)&owT_lo, g_outwT_lo);
    cudaGetSymbolAddress((void**)&wte_h,  g_wte_h);

    const int SM2 = STAGES * 3 * MAT_BYTES;
    const int SM1 = STAGES * 2 * MAT_BYTES;
    cudaFuncSetAttribute(gemm_h<2,0,1,0>, cudaFuncAttributeMaxDynamicSharedMemorySize, SM2);
    cudaFuncSetAttribute(gemm_h<2,0,0,1>, cudaFuncAttributeMaxDynamicSharedMemorySize, SM2);
    cudaFuncSetAttribute(gemm_h<2,1,1,0>, cudaFuncAttributeMaxDynamicSharedMemorySize, SM2);
    cudaFuncSetAttribute(gemm_h<1,0,0,0>, cudaFuncAttributeMaxDynamicSharedMemorySize, SM1);
    cudaFuncSetAttribute(flash_attn_kernel, cudaFuncAttributeMaxDynamicSharedMemorySize, ATT_SMEM);

    dim3 tb(32, 8);
    const dim3 gQKV(D3 / BN, MM / BM), gPROJ(DD / BN, MM / BM),
               gFC(D4 / BN, MM / BM),  gOUT(DD / BN, MM / BM),
               gLM((VV + BN - 1) / BN, MM / BM),
               gATT(TT / 64, HH, BB);

    // order: ncu (-s 5 -c 1) captures the 4th launch -> qkv GEMM (verify pipeline fix)
    conv_transpose_kernel<<<dim3(D3 / 32, DD / 32, LL), tb>>>(attn_w, awT_hi, awT_lo, DD, D3); // 1
    embed_ln_kernel<<<MM, 256>>>(ids, wte, wpe, ln1_g, ln1_b, x, h_h);                         // 2
    conv_wte_kernel<<<(VV * DD / 8 + 255) / 256, 256>>>(wte, wte_h, VV * DD / 8);              // 3
    gemm_h<2,0,1,0><<<gQKV, 256, SM2>>>(                                                       // 4 <- profiled
        h_h, awT_hi, awT_lo, attn_b, nullptr, nullptr, qkv_h, D3, DD);
    flash_attn_kernel<<<gATT, 256, ATT_SMEM>>>(qkv_h, at_h);                                   // 5
    conv_transpose_kernel<<<dim3(DD / 32, DD / 32, LL), tb>>>(proj_w, pwT_hi, pwT_lo, DD, DD); // 6
    conv_transpose_kernel<<<dim3(D4 / 32, DD / 32, LL), tb>>>(fc_w, fwT_hi, fwT_lo, DD, D4);   // 7
    conv_transpose_kernel<<<dim3(DD / 32, D4 / 32, LL), tb>>>(out_w, owT_hi, owT_lo, D4, DD);  // 8

    for (int l = 0; l < LL; l++) {
        if (l > 0) {
            layernorm_h_kernel<<<MM, 256>>>(x, ln1_g + l * DD, ln1_b + l * DD, h_h);
            gemm_h<2,0,1,0><<<gQKV, 256, SM2>>>(
                h_h, awT_hi + (size_t)l * D3 * DD, awT_lo + (size_t)l * D3 * DD,
                attn_b + (size_t)l * D3, nullptr, nullptr, qkv_h, D3, DD);
            flash_attn_kernel<<<gATT, 256, ATT_SMEM>>>(qkv_h, at_h);
        }

        gemm_h<2,0,0,1><<<gPROJ, 256, SM2>>>(
            at_h, pwT_hi + (size_t)l * DD * DD, pwT_lo + (size_t)l * DD * DD,
            proj_b + (size_t)l * DD, x, x, nullptr, DD, DD);

        layernorm_h_kernel<<<MM, 256>>>(x, ln2_g + l * DD, ln2_b + l * DD, h_h);

        gemm_h<2,1,1,0><<<gFC, 256, SM2>>>(
            h_h, fwT_hi + (size_t)l * D4 * DD, fwT_lo + (size_t)l * D4 * DD,
            fc_b + (size_t)l * D4, nullptr, nullptr, fc_h, D4, DD);

        gemm_h<2,0,0,1><<<gOUT, 256, SM2>>>(
            fc_h, owT_hi + (size_t)l * DD * D4, owT_lo + (size_t)l * DD * D4,
            out_b + (size_t)l * DD, x, x, nullptr, DD, D4);
    }

    layernorm_h_kernel<<<MM, 256>>>(x, lnf_g, lnf_b, h_h);

    gemm_h<1,0,0,0><<<gLM, 256, SM1>>>(
        h_h, wte_h, nullptr, nullptr, nullptr, logits, nullptr, VV, DD);
}